// round 5
// baseline (speedup 1.0000x reference)
#include <cuda_runtime.h>
#include <math.h>
#include <stdint.h>

// Problem constants
#define B_    4
#define C_    384
#define C3_   1152
#define CT_   1536        // 1152 qkv + 384 bs
#define HH_   128
#define WW_   128
#define P_    16384       // H*W
#define HEADS_ 8
#define CH_   48
#define BH_   32          // B*HEADS
#define SPLITS_ 16
#define K2_   768         // proj K
#define SCALE_ 0.14433756729740643f  // 1/sqrt(48)
#define QMAX_ 32512.0f    // 127*256

// Scratch (static device arrays; no cudaMalloc allowed)
__device__ float g_pw[(size_t)B_ * CT_ * P_];       // pointwise output (fp32)
__device__ float g_dw[(size_t)B_ * CT_ * P_];       // depthwise output (q,k,v,y)
__device__ float g_attnout[(size_t)B_ * C_ * P_];   // attn @ V (fp32)
__device__ float g_part[(size_t)BH_ * SPLITS_ * CH_ * CH_];
__device__ float g_norms[2 * B_ * C_];
__device__ float g_attn[(size_t)BH_ * CH_ * CH_];
// int8 split operands (K-major rows)
__device__ __align__(256) int8_t g_wA8h[(size_t)CT_ * C_];
__device__ __align__(256) int8_t g_wA8l[(size_t)CT_ * C_];
__device__ __align__(256) int8_t g_wP8h[(size_t)C_ * K2_];
__device__ __align__(256) int8_t g_wP8l[(size_t)C_ * K2_];
__device__ __align__(256) int8_t g_x8h[(size_t)B_ * P_ * C_];
__device__ __align__(256) int8_t g_x8l[(size_t)B_ * P_ * C_];
__device__ __align__(256) int8_t g_p8h[(size_t)B_ * P_ * K2_];
__device__ __align__(256) int8_t g_p8l[(size_t)B_ * P_ * K2_];
__device__ float g_swA[CT_];
__device__ float g_swP[C_];
__device__ float g_sx[(size_t)B_ * P_];
__device__ float g_sp[(size_t)B_ * P_];

// ---------------------------------------------------------------------------
// Helpers
// ---------------------------------------------------------------------------
__device__ __forceinline__ uint32_t smem_u32(const void* p) {
    uint32_t a;
    asm("{ .reg .u64 t; cvta.to.shared.u64 t, %1; cvt.u32.u64 %0, t; }"
        : "=r"(a) : "l"(p));
    return a;
}
__device__ __forceinline__ void cp16(uint32_t sa, const void* g) {
    asm volatile("cp.async.cg.shared.global [%0], [%1], 16;" :: "r"(sa), "l"(g));
}
#define CP_COMMIT() asm volatile("cp.async.commit_group;" ::: "memory")
#define CP_WAIT0()  asm volatile("cp.async.wait_group 0;" ::: "memory")

__device__ __forceinline__ void ldm_x4(uint32_t* r, uint32_t addr) {
    asm volatile("ldmatrix.sync.aligned.m8n8.x4.shared.b16 {%0,%1,%2,%3}, [%4];"
        : "=r"(r[0]), "=r"(r[1]), "=r"(r[2]), "=r"(r[3]) : "r"(addr));
}
__device__ __forceinline__ void mma_s8(int* c, const uint32_t* a, const uint32_t* b) {
    asm volatile("mma.sync.aligned.m16n8k32.row.col.s32.s8.s8.s32 "
        "{%0,%1,%2,%3}, {%4,%5,%6,%7}, {%8,%9}, {%0,%1,%2,%3};"
        : "+r"(c[0]), "+r"(c[1]), "+r"(c[2]), "+r"(c[3])
        : "r"(a[0]), "r"(a[1]), "r"(a[2]), "r"(a[3]), "r"(b[0]), "r"(b[1]));
}

// f32x2 helpers (FFMA2)
__device__ __forceinline__ void fma_f32x2(unsigned long long& d,
                                          unsigned long long a,
                                          unsigned long long b) {
    asm("fma.rn.f32x2 %0, %1, %2, %0;" : "+l"(d) : "l"(a), "l"(b));
}
__device__ __forceinline__ float f2lo(unsigned long long v) {
    return __uint_as_float((unsigned)v);
}
__device__ __forceinline__ float f2hi(unsigned long long v) {
    return __uint_as_float((unsigned)(v >> 32));
}

// quantize one value (already scaled by inv): returns packed (hi, lo) int8
__device__ __forceinline__ void quant1(float v, int& hi, int& lo) {
    v = fminf(fmaxf(v, -QMAX_), QMAX_);
    int qi = __float2int_rn(v);
    hi = (qi + 128) >> 8;          // arithmetic shift = floor div
    lo = qi - (hi << 8);           // in [-128, 127]
}

// ---------------------------------------------------------------------------
// Weight quantization: one warp per output row (per-row scale over K)
// rows 0..CT_-1 : fused pw weights (K=384); rows CT_.. : proj (K=768)
// ---------------------------------------------------------------------------
__global__ __launch_bounds__(256) void quant_w_kernel(
    const float* __restrict__ w_qkv,
    const float* __restrict__ w_bs_pw,
    const float* __restrict__ w_proj)
{
    int row  = blockIdx.x * 8 + (threadIdx.x >> 5);
    int lane = threadIdx.x & 31;
    const float* src;
    int K;
    int8_t *dh, *dl;
    float* sdst;
    if (row < CT_) {
        K = C_;
        src = (row < C3_) ? (w_qkv + (size_t)row * C_)
                          : (w_bs_pw + (size_t)(row - C3_) * C_);
        dh = g_wA8h + (size_t)row * C_;
        dl = g_wA8l + (size_t)row * C_;
        sdst = g_swA + row;
    } else {
        int m = row - CT_;
        if (m >= C_) return;
        K = K2_;
        src = w_proj + (size_t)m * K2_;
        dh = g_wP8h + (size_t)m * K2_;
        dl = g_wP8l + (size_t)m * K2_;
        sdst = g_swP + m;
    }
    float mx = 0.f;
    for (int k = lane; k < K; k += 32) mx = fmaxf(mx, fabsf(src[k]));
    #pragma unroll
    for (int off = 16; off > 0; off >>= 1)
        mx = fmaxf(mx, __shfl_xor_sync(0xFFFFFFFFu, mx, off));
    float inv = (mx > 0.f) ? (QMAX_ / mx) : 0.f;
    if (lane == 0) *sdst = mx / QMAX_;
    for (int k = lane; k < K; k += 32) {
        int hi, lo;
        quant1(src[k] * inv, hi, lo);
        dh[k] = (int8_t)hi;
        dl[k] = (int8_t)lo;
    }
}

// ---------------------------------------------------------------------------
// Activation quantization: transpose [c][p] fp32 -> [p][k] int8 hi/lo with
// per-pixel scale over all K channels. Block = 32 pixels, 256 threads.
// MODE 0: x (K=384) -> g_x8*, g_sx ; MODE 1: cat(attnout, y) (K=768) -> g_p8*
// ---------------------------------------------------------------------------
template <int MODE>
__global__ __launch_bounds__(256) void quant_act_kernel(const float* __restrict__ x)
{
    const int K = (MODE == 0) ? C_ : K2_;
    extern __shared__ float QS[];                 // [K][33] + red[256] + inv[32]
    float* red  = QS + K * 33;
    float* sinv = red + 256;

    const int p0  = blockIdx.x * 32;
    const int b   = blockIdx.y;
    const int tid = threadIdx.x;

    const int nld = (K * 32) / 256;
    for (int e = 0; e < nld; e++) {
        int idx = tid + e * 256;
        int c = idx >> 5, pc = idx & 31;
        float v;
        if (MODE == 0) {
            v = x[((size_t)b * C_ + c) * P_ + p0 + pc];
        } else {
            v = (c < C_) ? g_attnout[((size_t)b * C_ + c) * P_ + p0 + pc]
                         : g_dw[((size_t)b * CT_ + C3_ + (c - C_)) * P_ + p0 + pc];
        }
        QS[c * 33 + pc] = v;
    }
    __syncthreads();

    const int j  = tid & 7;        // 8 threads per pixel
    const int pc = tid >> 3;       // 0..31
    const int per = K / 8;         // 48 or 96 channels per thread
    float mx = 0.f;
    for (int i = 0; i < per; i++) {
        int c = j + 8 * i;
        mx = fmaxf(mx, fabsf(QS[c * 33 + pc]));
    }
    red[pc * 8 + j] = mx;
    __syncthreads();
    if (j == 0) {
        float mm = red[pc * 8];
        #pragma unroll
        for (int q = 1; q < 8; q++) mm = fmaxf(mm, red[pc * 8 + q]);
        float* sc = (MODE == 0) ? g_sx : g_sp;
        sc[(size_t)b * P_ + p0 + pc] = mm / QMAX_;
        sinv[pc] = (mm > 0.f) ? (QMAX_ / mm) : 0.f;
    }
    __syncthreads();
    float inv = sinv[pc];

    int8_t* dh = ((MODE == 0) ? g_x8h : g_p8h) + ((size_t)b * P_ + p0 + pc) * K + j * per;
    int8_t* dl = ((MODE == 0) ? g_x8l : g_p8l) + ((size_t)b * P_ + p0 + pc) * K + j * per;
    for (int q = 0; q < per / 4; q++) {
        uint32_t hu = 0, lu = 0;
        #pragma unroll
        for (int t2 = 0; t2 < 4; t2++) {
            int k = j * per + q * 4 + t2;
            int hi, lo;
            quant1(QS[k * 33 + pc] * inv, hi, lo);
            hu |= ((uint32_t)(uint8_t)(int8_t)hi) << (8 * t2);
            lu |= ((uint32_t)(uint8_t)(int8_t)lo) << (8 * t2);
        }
        *(uint32_t*)(dh + q * 4) = hu;
        *(uint32_t*)(dl + q * 4) = lu;
    }
}

// ---------------------------------------------------------------------------
// Int8 split-MMA GEMM: D[M,N] = A[M,K] @ B[N,K]^T, dequantized fp32 out.
// CTA 128x128, 256 threads, 8 warps (4m x 2n, 32x64 each), K chunk = 64,
// cp.async double-buffered. D = sa[m]*sb[n]*(65536*acc_hh + 256*acc_x).
// MODE 0: pw  (M=1536, K=384, out=g_pw); MODE 1: proj (M=384, K=768, out)
// ---------------------------------------------------------------------------
#define RS 80                       // padded row stride (64 data + 16 pad)
#define TILEB (128 * RS)            // 10240
#define STAGEB (4 * TILEB)          // 40960
#define GSMEM (2 * STAGEB)          // 81920

template <int MODE>
__global__ __launch_bounds__(256) void gemm_i8_kernel(float* __restrict__ outp)
{
    extern __shared__ __align__(16) char S[];
    const int Kdim = (MODE == 0) ? C_ : K2_;
    const int Mdim = (MODE == 0) ? CT_ : C_;
    const int b  = blockIdx.z;
    const int n0 = blockIdx.x * 128;
    const int m0 = blockIdx.y * 128;

    const int8_t* Ah = (MODE == 0) ? g_wA8h : g_wP8h;
    const int8_t* Al = (MODE == 0) ? g_wA8l : g_wP8l;
    const int8_t* Bh = ((MODE == 0) ? g_x8h : g_p8h) + (size_t)b * P_ * Kdim;
    const int8_t* Bl = ((MODE == 0) ? g_x8l : g_p8l) + (size_t)b * P_ * Kdim;
    const float* sa_arr = (MODE == 0) ? g_swA : g_swP;
    const float* sb_arr = ((MODE == 0) ? g_sx : g_sp) + (size_t)b * P_;

    const int tid  = threadIdx.x;
    const int lane = tid & 31, warp = tid >> 5;
    const int wm = warp >> 1, wn = warp & 1;
    const uint32_t sbase = smem_u32(S);

    int acc_hh[2][8][4], acc_x[2][8][4];
    #pragma unroll
    for (int mt = 0; mt < 2; mt++)
        #pragma unroll
        for (int nt = 0; nt < 8; nt++)
            #pragma unroll
            for (int q = 0; q < 4; q++) { acc_hh[mt][nt][q] = 0; acc_x[mt][nt][q] = 0; }

    const int nch = Kdim / 64;
    // per-thread cp.async mapping: 8 x 16B
    const int ct = tid >> 9;       (void)ct;

    // prologue (stage 0, k0 = 0)
    {
        const int8_t* gp[4] = { Ah + (size_t)m0 * Kdim, Al + (size_t)m0 * Kdim,
                                Bh + (size_t)n0 * Kdim, Bl + (size_t)n0 * Kdim };
        #pragma unroll
        for (int e = 0; e < 8; e++) {
            int idx = tid + e * 256;
            int t  = idx >> 9;
            int r  = (idx >> 2) & 127;
            int sg = idx & 3;
            uint32_t sa = sbase + t * TILEB + r * RS + sg * 16;
            cp16(sa, gp[t] + (size_t)r * Kdim + sg * 16);
        }
        CP_COMMIT();
    }

    for (int c = 0; c < nch; c++) {
        CP_WAIT0();
        __syncthreads();

        if (c + 1 < nch) {
            int k0 = (c + 1) * 64;
            int st = (c + 1) & 1;
            const int8_t* gp[4] = { Ah + (size_t)m0 * Kdim, Al + (size_t)m0 * Kdim,
                                    Bh + (size_t)n0 * Kdim, Bl + (size_t)n0 * Kdim };
            #pragma unroll
            for (int e = 0; e < 8; e++) {
                int idx = tid + e * 256;
                int t  = idx >> 9;
                int r  = (idx >> 2) & 127;
                int sg = idx & 3;
                uint32_t sa = sbase + st * STAGEB + t * TILEB + r * RS + sg * 16;
                cp16(sa, gp[t] + (size_t)r * Kdim + k0 + sg * 16);
            }
            CP_COMMIT();
        }

        const uint32_t stb = sbase + (c & 1) * STAGEB;
        const uint32_t bAh = stb;
        const uint32_t bAl = stb + TILEB;
        const uint32_t bBh = stb + 2 * TILEB;
        const uint32_t bBl = stb + 3 * TILEB;

        #pragma unroll
        for (int kk = 0; kk < 2; kk++) {
            const int kob = kk * 32 + (lane >> 4) * 16;   // byte offset in row
            const int ar = wm * 32 + (lane & 15);
            uint32_t a_h[2][4], a_l[2][4];
            #pragma unroll
            for (int mt = 0; mt < 2; mt++) {
                ldm_x4(a_h[mt], bAh + (ar + mt * 16) * RS + kob);
                ldm_x4(a_l[mt], bAl + (ar + mt * 16) * RS + kob);
            }
            uint32_t b_h[8][2], b_l[8][2];
            #pragma unroll
            for (int nt2 = 0; nt2 < 4; nt2++) {
                const int br = wn * 64 + nt2 * 16 + (lane & 15);
                uint32_t r4[4];
                ldm_x4(r4, bBh + br * RS + kob);
                b_h[nt2 * 2][0] = r4[0]; b_h[nt2 * 2 + 1][0] = r4[1];
                b_h[nt2 * 2][1] = r4[2]; b_h[nt2 * 2 + 1][1] = r4[3];
                ldm_x4(r4, bBl + br * RS + kob);
                b_l[nt2 * 2][0] = r4[0]; b_l[nt2 * 2 + 1][0] = r4[1];
                b_l[nt2 * 2][1] = r4[2]; b_l[nt2 * 2 + 1][1] = r4[3];
            }
            #pragma unroll
            for (int mt = 0; mt < 2; mt++)
                #pragma unroll
                for (int nt = 0; nt < 8; nt++) {
                    mma_s8(acc_hh[mt][nt], a_h[mt], b_h[nt]);
                    mma_s8(acc_x[mt][nt],  a_h[mt], b_l[nt]);
                    mma_s8(acc_x[mt][nt],  a_l[mt], b_h[nt]);
                }
        }
        __syncthreads();
    }

    // epilogue: dequantize + store fp32
    float* outb = outp + (size_t)b * Mdim * P_;
    #pragma unroll
    for (int mt = 0; mt < 2; mt++) {
        int r1 = m0 + wm * 32 + mt * 16 + (lane >> 2);
        float sa0 = sa_arr[r1];
        float sa1 = sa_arr[r1 + 8];
        #pragma unroll
        for (int nt = 0; nt < 8; nt++) {
            int col = n0 + wn * 64 + nt * 8 + 2 * (lane & 3);
            float sb0 = sb_arr[col];
            float sb1 = sb_arr[col + 1];
            float v00 = sa0 * sb0 * (65536.f * (float)acc_hh[mt][nt][0] + 256.f * (float)acc_x[mt][nt][0]);
            float v01 = sa0 * sb1 * (65536.f * (float)acc_hh[mt][nt][1] + 256.f * (float)acc_x[mt][nt][1]);
            float v10 = sa1 * sb0 * (65536.f * (float)acc_hh[mt][nt][2] + 256.f * (float)acc_x[mt][nt][2]);
            float v11 = sa1 * sb1 * (65536.f * (float)acc_hh[mt][nt][3] + 256.f * (float)acc_x[mt][nt][3]);
            *(float2*)&outb[(size_t)r1 * P_ + col]       = make_float2(v00, v01);
            *(float2*)&outb[(size_t)(r1 + 8) * P_ + col] = make_float2(v10, v11);
        }
    }
}

// ---------------------------------------------------------------------------
// Depthwise 3x3 conv (pad 1) + exact GELU on bs channels, 16-row tiles
// ---------------------------------------------------------------------------
__global__ __launch_bounds__(256) void dw_kernel(
    const float* __restrict__ w_dw,
    const float* __restrict__ w_bs_dw)
{
    __shared__ float s[18][128];
    const int y0 = blockIdx.x * 16;
    const int ch = blockIdx.y;
    const int b  = blockIdx.z;
    const int tid = threadIdx.x;

    const float* in = g_pw + ((size_t)b * CT_ + ch) * P_;
    #pragma unroll
    for (int e = 0; e < 9; e++) {
        int idx = tid + e * 256;
        int row = idx >> 7, col = idx & 127;
        int y = y0 - 1 + row;
        s[row][col] = (y >= 0 && y < HH_) ? in[y * WW_ + col] : 0.f;
    }
    __syncthreads();

    const float* wp = (ch < C3_) ? (w_dw + ch * 9) : (w_bs_dw + (ch - C3_) * 9);
    float w[9];
    #pragma unroll
    for (int i = 0; i < 9; i++) w[i] = __ldg(&wp[i]);

    float* outc = g_dw + ((size_t)b * CT_ + ch) * P_;
    const int x = tid & 127;
    #pragma unroll
    for (int i = 0; i < 8; i++) {
        int r = 2 * i + (tid >> 7);
        const float* s0 = s[r];
        const float* s1 = s[r + 1];
        const float* s2 = s[r + 2];
        float acc = w[1] * s0[x] + w[4] * s1[x] + w[7] * s2[x];
        if (x > 0)
            acc += w[0] * s0[x - 1] + w[3] * s1[x - 1] + w[6] * s2[x - 1];
        if (x < 127)
            acc += w[2] * s0[x + 1] + w[5] * s1[x + 1] + w[8] * s2[x + 1];
        if (ch >= C3_)
            acc = 0.5f * acc * (1.0f + erff(acc * 0.70710678118654752f));
        outc[(y0 + r) * WW_ + x] = acc;
    }
}

// ---------------------------------------------------------------------------
// L2 norms of q and k rows
// ---------------------------------------------------------------------------
__global__ __launch_bounds__(256) void norm_kernel()
{
    const int bid = blockIdx.x;
    const int isk = bid >= B_ * C_;
    const int v   = isk ? bid - B_ * C_ : bid;
    const int b   = v / C_, c = v % C_;
    const float* src = g_dw + ((size_t)b * CT_ + (isk ? C_ + c : c)) * P_;

    float s = 0.f;
    for (int i = threadIdx.x; i < P_; i += 256) {
        float t = src[i];
        s += t * t;
    }
    __shared__ float red[256];
    red[threadIdx.x] = s;
    __syncthreads();
    for (int off = 128; off > 0; off >>= 1) {
        if (threadIdx.x < off) red[threadIdx.x] += red[threadIdx.x + off];
        __syncthreads();
    }
    if (threadIdx.x == 0) g_norms[bid] = fmaxf(sqrtf(red[0]), 1e-12f);
}

// ---------------------------------------------------------------------------
// Attention logits split-K partials (f32x2)
// ---------------------------------------------------------------------------
__global__ __launch_bounds__(256) void attn_part_kernel()
{
    const int s  = blockIdx.x;   // 0..15
    const int bh = blockIdx.y;   // 0..31
    const int b = bh >> 3, h = bh & 7;

    const float* qb = g_dw + ((size_t)b * CT_ + h * CH_) * P_ + s * 1024;
    const float* kb = g_dw + ((size_t)b * CT_ + C_ + h * CH_) * P_ + s * 1024;

    __shared__ __align__(16) float qs[48][66];
    __shared__ __align__(16) float ks[48][66];

    const int tid = threadIdx.x;
    const int tx = tid & 15, ty = tid >> 4;
    const int i0 = ty * 3, j0 = tx * 3;
    unsigned long long acc[3][3];
    #pragma unroll
    for (int i = 0; i < 3; i++)
        #pragma unroll
        for (int jj = 0; jj < 3; jj++) acc[i][jj] = 0ull;

    for (int p0 = 0; p0 < 1024; p0 += 64) {
        #pragma unroll
        for (int e = 0; e < 12; e++) {
            int idx = tid + e * 256;
            int row = idx >> 6, col = idx & 63;
            qs[row][col] = qb[(size_t)row * P_ + p0 + col];
            ks[row][col] = kb[(size_t)row * P_ + p0 + col];
        }
        __syncthreads();
        #pragma unroll 8
        for (int p = 0; p < 64; p += 2) {
            unsigned long long a0 = __double_as_longlong(*(const double*)&qs[i0][p]);
            unsigned long long a1 = __double_as_longlong(*(const double*)&qs[i0 + 1][p]);
            unsigned long long a2 = __double_as_longlong(*(const double*)&qs[i0 + 2][p]);
            unsigned long long b0 = __double_as_longlong(*(const double*)&ks[j0][p]);
            unsigned long long b1 = __double_as_longlong(*(const double*)&ks[j0 + 1][p]);
            unsigned long long b2 = __double_as_longlong(*(const double*)&ks[j0 + 2][p]);
            fma_f32x2(acc[0][0], a0, b0); fma_f32x2(acc[0][1], a0, b1); fma_f32x2(acc[0][2], a0, b2);
            fma_f32x2(acc[1][0], a1, b0); fma_f32x2(acc[1][1], a1, b1); fma_f32x2(acc[1][2], a1, b2);
            fma_f32x2(acc[2][0], a2, b0); fma_f32x2(acc[2][1], a2, b1); fma_f32x2(acc[2][2], a2, b2);
        }
        __syncthreads();
    }

    float* out = g_part + ((size_t)bh * SPLITS_ + s) * (CH_ * CH_);
    #pragma unroll
    for (int i = 0; i < 3; i++)
        #pragma unroll
        for (int jj = 0; jj < 3; jj++)
            out[(i0 + i) * CH_ + j0 + jj] = f2lo(acc[i][jj]) + f2hi(acc[i][jj]);
}

// ---------------------------------------------------------------------------
// Softmax rows (with normalization by q/k norms and scale)
// ---------------------------------------------------------------------------
__global__ __launch_bounds__(64) void softmax_kernel()
{
    const int i  = blockIdx.x;
    const int bh = blockIdx.y;
    const int b = bh >> 3, h = bh & 7;
    const int j = threadIdx.x;

    float val = 0.f;
    float logit = -1e30f;
    if (j < CH_) {
        float sum = 0.f;
        #pragma unroll
        for (int s = 0; s < SPLITS_; s++)
            sum += g_part[((size_t)bh * SPLITS_ + s) * (CH_ * CH_) + i * CH_ + j];
        float nq = g_norms[b * C_ + h * CH_ + i];
        float nk = g_norms[B_ * C_ + b * C_ + h * CH_ + j];
        val = sum / (nq * nk) * SCALE_;
        logit = val;
    }
    __shared__ float red[64];
    red[j] = logit;
    __syncthreads();
    for (int off = 32; off > 0; off >>= 1) {
        if (j < off) red[j] = fmaxf(red[j], red[j + off]);
        __syncthreads();
    }
    float mx = red[0];
    __syncthreads();
    float e = (j < CH_) ? expf(val - mx) : 0.f;
    red[j] = e;
    __syncthreads();
    for (int off = 32; off > 0; off >>= 1) {
        if (j < off) red[j] += red[j + off];
        __syncthreads();
    }
    if (j < CH_) g_attn[(size_t)bh * CH_ * CH_ + i * CH_ + j] = e / red[0];
}

// ---------------------------------------------------------------------------
// out = attn @ V (fp32 into g_attnout)
// ---------------------------------------------------------------------------
__global__ __launch_bounds__(128) void av_kernel()
{
    const int pb = blockIdx.x;
    const int bh = blockIdx.y;
    const int b = bh >> 3, h = bh & 7;
    const int p = pb * 128 + threadIdx.x;

    __shared__ float at[CH_ * CH_];
    for (int idx = threadIdx.x; idx < CH_ * CH_; idx += 128)
        at[idx] = g_attn[(size_t)bh * CH_ * CH_ + idx];
    __syncthreads();

    const float* vb = g_dw + ((size_t)b * CT_ + 2 * C_ + h * CH_) * P_ + p;
    float v[CH_];
    #pragma unroll
    for (int d = 0; d < CH_; d++) v[d] = vb[(size_t)d * P_];

    float* ob = g_attnout + ((size_t)b * C_ + h * CH_) * P_ + p;
    #pragma unroll 4
    for (int c = 0; c < CH_; c++) {
        float acc = 0.f;
        #pragma unroll
        for (int d = 0; d < CH_; d++) acc += at[c * CH_ + d] * v[d];
        ob[(size_t)c * P_] = acc;
    }
}

// ---------------------------------------------------------------------------
extern "C" void kernel_launch(void* const* d_in, const int* in_sizes, int n_in,
                              void* d_out, int out_size)
{
    const float* x       = (const float*)d_in[0];
    const float* w_qkv   = (const float*)d_in[1];
    const float* w_dw    = (const float*)d_in[2];
    const float* w_proj  = (const float*)d_in[3];
    const float* w_bs_pw = (const float*)d_in[4];
    const float* w_bs_dw = (const float*)d_in[5];
    float* out = (float*)d_out;

    const int QX_SMEM = C_ * 33 * 4 + 256 * 4 + 32 * 4;   // 51,840
    const int QP_SMEM = K2_ * 33 * 4 + 256 * 4 + 32 * 4;  // 102,528

    cudaFuncSetAttribute(gemm_i8_kernel<0>,
                         cudaFuncAttributeMaxDynamicSharedMemorySize, GSMEM);
    cudaFuncSetAttribute(gemm_i8_kernel<1>,
                         cudaFuncAttributeMaxDynamicSharedMemorySize, GSMEM);
    cudaFuncSetAttribute(quant_act_kernel<0>,
                         cudaFuncAttributeMaxDynamicSharedMemorySize, QX_SMEM);
    cudaFuncSetAttribute(quant_act_kernel<1>,
                         cudaFuncAttributeMaxDynamicSharedMemorySize, QP_SMEM);

    float* pw = nullptr;
    cudaGetSymbolAddress((void**)&pw, g_pw);

    // 0) quantize weights (per-row scale) and x (per-pixel scale)
    quant_w_kernel<<<(CT_ + C_) / 8, 256>>>(w_qkv, w_bs_pw, w_proj);
    quant_act_kernel<0><<<dim3(P_ / 32, B_), 256, QX_SMEM>>>(x);
    // 1) fused pointwise GEMM (int8 split MMA)
    gemm_i8_kernel<0><<<dim3(P_ / 128, CT_ / 128, B_), 256, GSMEM>>>(pw);
    // 2) depthwise 3x3 (+GELU on bs channels)
    dw_kernel<<<dim3(HH_ / 16, CT_, B_), 256>>>(w_dw, w_bs_dw);
    // 3) q/k L2 norms
    norm_kernel<<<2 * B_ * C_, 256>>>();
    // 4) attention logits (split-K partials, f32x2)
    attn_part_kernel<<<dim3(SPLITS_, BH_), 256>>>();
    // 5) softmax with normalization
    softmax_kernel<<<dim3(CH_, BH_), 64>>>();
    // 6) attn @ V -> g_attnout (fp32)
    av_kernel<<<dim3(P_ / 128, BH_), 128>>>();
    // 6b) quantize cat(attnout, y) per-pixel over K=768
    quant_act_kernel<1><<<dim3(P_ / 32, B_), 256, QP_SMEM>>>(nullptr);
    // 7) projection GEMM (int8) -> output
    gemm_i8_kernel<1><<<dim3(P_ / 128, C_ / 128, B_), 256, GSMEM>>>(out);
}

// round 6
// speedup vs baseline: 1.9068x; 1.9068x over previous
#include <cuda_runtime.h>
#include <cuda_fp16.h>
#include <math.h>
#include <stdint.h>

// Problem constants
#define B_    4
#define C_    384
#define C3_   1152
#define CT_   1536        // 1152 qkv + 384 bs
#define HH_   128
#define WW_   128
#define P_    16384       // H*W
#define HEADS_ 8
#define CH_   48
#define SPLITS_ 16
#define SCALE_ 0.14433756729740643f  // 1/sqrt(48)

#define LDK 40            // padded K stride (halfs) in GEMM smem tiles

// Scratch (static device arrays; no cudaMalloc allowed)
__device__ float g_pw[(size_t)B_ * CT_ * P_];       // pointwise output (fp32)
__device__ float g_dw[(size_t)B_ * CT_ * P_];       // depthwise output (q,k,v,y)
__device__ float g_part[(size_t)B_ * HEADS_ * SPLITS_ * CH_ * CH_];
__device__ float g_norms[2 * B_ * C_];
__device__ float g_attn[(size_t)B_ * HEADS_ * CH_ * CH_];
// fp16 hi/lo split operands for tensor-core GEMMs (K-major)
__device__ __align__(256) __half g_wA_h[(size_t)CT_ * C_];      // [m][k] fused qkv+bs
__device__ __align__(256) __half g_wA_l[(size_t)CT_ * C_];
__device__ __align__(256) __half g_wP_h[(size_t)C_ * 2 * C_];   // [m][k] proj
__device__ __align__(256) __half g_wP_l[(size_t)C_ * 2 * C_];
__device__ __align__(256) __half g_xT_h[(size_t)B_ * P_ * C_];  // [b][p][k]
__device__ __align__(256) __half g_xT_l[(size_t)B_ * P_ * C_];
__device__ __align__(256) __half g_pT_h[(size_t)B_ * P_ * 2 * C_]; // [b][p][k]
__device__ __align__(256) __half g_pT_l[(size_t)B_ * P_ * 2 * C_];

// ---------------------------------------------------------------------------
// Helpers
// ---------------------------------------------------------------------------
__device__ __forceinline__ uint32_t smem_u32(const void* p) {
    uint32_t a;
    asm("{ .reg .u64 t; cvta.to.shared.u64 t, %1; cvt.u32.u64 %0, t; }"
        : "=r"(a) : "l"(p));
    return a;
}
__device__ __forceinline__ void cp16(uint32_t sa, const void* g) {
    asm volatile("cp.async.cg.shared.global [%0], [%1], 16;" :: "r"(sa), "l"(g));
}
#define CP_COMMIT() asm volatile("cp.async.commit_group;" ::: "memory")
#define CP_WAIT0()  asm volatile("cp.async.wait_group 0;" ::: "memory")

__device__ __forceinline__ void ldm_x4(uint32_t* r, uint32_t addr) {
    asm volatile("ldmatrix.sync.aligned.m8n8.x4.shared.b16 {%0,%1,%2,%3}, [%4];"
        : "=r"(r[0]), "=r"(r[1]), "=r"(r[2]), "=r"(r[3]) : "r"(addr));
}
__device__ __forceinline__ void mma16816(float* c, const uint32_t* a, const uint32_t* b) {
    asm volatile("mma.sync.aligned.m16n8k16.row.col.f32.f16.f16.f32 "
        "{%0,%1,%2,%3}, {%4,%5,%6,%7}, {%8,%9}, {%0,%1,%2,%3};"
        : "+f"(c[0]), "+f"(c[1]), "+f"(c[2]), "+f"(c[3])
        : "r"(a[0]), "r"(a[1]), "r"(a[2]), "r"(a[3]), "r"(b[0]), "r"(b[1]));
}

// f32x2 helpers (FFMA2)
__device__ __forceinline__ void fma_f32x2(unsigned long long& d,
                                          unsigned long long a,
                                          unsigned long long b) {
    asm("fma.rn.f32x2 %0, %1, %2, %0;" : "+l"(d) : "l"(a), "l"(b));
}
__device__ __forceinline__ float f2lo(unsigned long long v) {
    return __uint_as_float((unsigned)v);
}
__device__ __forceinline__ float f2hi(unsigned long long v) {
    return __uint_as_float((unsigned)(v >> 32));
}

__device__ __forceinline__ void split_h(float v, __half& h, __half& l) {
    h = __float2half(v);
    l = __float2half(v - __half2float(h));
}
__device__ __forceinline__ uint32_t pack_h(__half a, __half b) {
    return (uint32_t)__half_as_ushort(a) | ((uint32_t)__half_as_ushort(b) << 16);
}

// ---------------------------------------------------------------------------
// Weight convert: hi/lo fp16, native [m][k] layout
// ---------------------------------------------------------------------------
__global__ __launch_bounds__(256) void conv_w_kernel(
    const float* __restrict__ w_qkv,
    const float* __restrict__ w_bs_pw,
    const float* __restrict__ w_proj)
{
    const int nA = CT_ * C_;       // 589824
    const int nP = C_ * 2 * C_;    // 294912
    int idx = blockIdx.x * 256 + threadIdx.x;
    if (idx < nA) {
        int m = idx / C_, k = idx % C_;
        float v = (m < C3_) ? w_qkv[m * C_ + k] : w_bs_pw[(m - C3_) * C_ + k];
        __half h, l; split_h(v, h, l);
        g_wA_h[idx] = h; g_wA_l[idx] = l;
    } else if (idx < nA + nP) {
        int j = idx - nA;
        float v = w_proj[j];
        __half h, l; split_h(v, h, l);
        g_wP_h[j] = h; g_wP_l[j] = l;
    }
}

// ---------------------------------------------------------------------------
// Transpose+convert x: [b][c][p] fp32 -> [b][p][c] hi/lo fp16
// grid (P/64, C/96, B), 256 threads
// ---------------------------------------------------------------------------
__global__ __launch_bounds__(256) void pack_x_kernel(const float* __restrict__ x)
{
    __shared__ __align__(16) float s[96][68];
    const int p0  = blockIdx.x * 64;
    const int ci0 = blockIdx.y * 96;
    const int b   = blockIdx.z;
    const int tid = threadIdx.x;

    #pragma unroll
    for (int e = 0; e < 24; e++) {
        int idx = tid + e * 256;
        int row = idx >> 6, col = idx & 63;
        s[row][col] = x[((size_t)b * C_ + ci0 + row) * P_ + p0 + col];
    }
    __syncthreads();

    const int px = tid & 63, part = tid >> 6;       // 4 parts x 24 ch
    size_t base = ((size_t)b * P_ + p0 + px) * C_ + ci0 + part * 24;
    uint32_t hb[12], lb[12];
    #pragma unroll
    for (int k = 0; k < 12; k++) {
        float v0 = s[part * 24 + 2 * k][px];
        float v1 = s[part * 24 + 2 * k + 1][px];
        __half h0, l0, h1, l1;
        split_h(v0, h0, l0); split_h(v1, h1, l1);
        hb[k] = pack_h(h0, h1); lb[k] = pack_h(l0, l1);
    }
    uint4* dh = (uint4*)&g_xT_h[base];
    uint4* dl = (uint4*)&g_xT_l[base];
    #pragma unroll
    for (int q = 0; q < 3; q++) {
        dh[q] = *(uint4*)&hb[q * 4];
        dl[q] = *(uint4*)&lb[q * 4];
    }
}

// ---------------------------------------------------------------------------
// Transpose+convert y (bs branch) into proj input cols 384..767 (per batch)
// grid (P/64, 384/96), 256 threads
// ---------------------------------------------------------------------------
__global__ __launch_bounds__(256) void pack_proj_kernel(int b)
{
    __shared__ __align__(16) float s[96][68];
    const int p0  = blockIdx.x * 64;
    const int ci0 = blockIdx.y * 96;
    const int tid = threadIdx.x;

    #pragma unroll
    for (int e = 0; e < 24; e++) {
        int idx = tid + e * 256;
        int row = idx >> 6, col = idx & 63;
        s[row][col] = g_dw[((size_t)b * CT_ + C3_ + ci0 + row) * P_ + p0 + col];
    }
    __syncthreads();

    const int px = tid & 63, part = tid >> 6;
    size_t base = ((size_t)b * P_ + p0 + px) * (2 * C_) + C_ + ci0 + part * 24;
    uint32_t hb[12], lb[12];
    #pragma unroll
    for (int k = 0; k < 12; k++) {
        float v0 = s[part * 24 + 2 * k][px];
        float v1 = s[part * 24 + 2 * k + 1][px];
        __half h0, l0, h1, l1;
        split_h(v0, h0, l0); split_h(v1, h1, l1);
        hb[k] = pack_h(h0, h1); lb[k] = pack_h(l0, l1);
    }
    uint4* dh = (uint4*)&g_pT_h[base];
    uint4* dl = (uint4*)&g_pT_l[base];
    #pragma unroll
    for (int q = 0; q < 3; q++) {
        dh[q] = *(uint4*)&hb[q * 4];
        dl[q] = *(uint4*)&lb[q * 4];
    }
}

// ---------------------------------------------------------------------------
// HMMA GEMM with fp16 3-term split: D[M,N] = A[M,K] @ B[N,K]^T (fp32 accum)
// CTA tile 128x128x32, 256 threads (8 warps = 4m x 2n, 32x64 each),
// cp.async double-buffered. Per-batch launch (b passed as arg).
// MODE 0: pw  (A=wA, B=xT, M=1536, K=384, out=g_pw)
// MODE 1: proj(A=wP, B=pT, M=384,  K=768, out=d_out)
// ---------------------------------------------------------------------------
#define TILE_BYTES (128 * LDK * 2)          // 10240
#define STAGE_BYTES (4 * TILE_BYTES)        // Ah, Al, Bh, Bl
#define GEMM_SMEM (2 * STAGE_BYTES)         // 81920

template <int MODE>
__global__ __launch_bounds__(256) void gemm_mma_kernel(float* __restrict__ outp, int b)
{
    extern __shared__ __align__(16) char S[];
    const int Kdim = (MODE == 0) ? C_ : 2 * C_;
    const int Mdim = (MODE == 0) ? CT_ : C_;
    const int n0 = blockIdx.x * 128;
    const int m0 = blockIdx.y * 128;

    const __half* Ah = (MODE == 0) ? g_wA_h : g_wP_h;
    const __half* Al = (MODE == 0) ? g_wA_l : g_wP_l;
    const __half* Bh = ((MODE == 0) ? g_xT_h : g_pT_h) + (size_t)b * P_ * Kdim;
    const __half* Bl = ((MODE == 0) ? g_xT_l : g_pT_l) + (size_t)b * P_ * Kdim;

    const int tid  = threadIdx.x;
    const int lane = tid & 31, warp = tid >> 5;
    const int wm = warp >> 1, wn = warp & 1;
    const uint32_t sbase = smem_u32(S);

    float acc[2][8][4];
    #pragma unroll
    for (int mt = 0; mt < 2; mt++)
        #pragma unroll
        for (int nt = 0; nt < 8; nt++)
            #pragma unroll
            for (int q = 0; q < 4; q++) acc[mt][nt][q] = 0.f;

    const int nch = Kdim / 32;
    const int lrow = tid >> 2;          // 0..63 (x2 with e)
    const int lq   = tid & 3;

    // ---- prologue load (stage 0, chunk 0)
    {
        const __half* gp[4] = { Ah + (size_t)m0 * Kdim, Al + (size_t)m0 * Kdim,
                                Bh + (size_t)n0 * Kdim, Bl + (size_t)n0 * Kdim };
        #pragma unroll
        for (int t = 0; t < 4; t++)
            #pragma unroll
            for (int e = 0; e < 2; e++) {
                int row = lrow + e * 64;
                uint32_t sa = sbase + t * TILE_BYTES + (row * LDK + lq * 8) * 2;
                cp16(sa, gp[t] + (size_t)row * Kdim + lq * 8);
            }
        CP_COMMIT();
    }

    for (int c = 0; c < nch; c++) {
        CP_WAIT0();
        __syncthreads();

        // issue next stage load (overlaps with compute below)
        if (c + 1 < nch) {
            int k0 = (c + 1) * 32;
            int st = (c + 1) & 1;
            const __half* gp[4] = { Ah + (size_t)m0 * Kdim, Al + (size_t)m0 * Kdim,
                                    Bh + (size_t)n0 * Kdim, Bl + (size_t)n0 * Kdim };
            #pragma unroll
            for (int t = 0; t < 4; t++)
                #pragma unroll
                for (int e = 0; e < 2; e++) {
                    int row = lrow + e * 64;
                    uint32_t sa = sbase + st * STAGE_BYTES + t * TILE_BYTES
                                + (row * LDK + lq * 8) * 2;
                    cp16(sa, gp[t] + (size_t)row * Kdim + k0 + lq * 8);
                }
            CP_COMMIT();
        }

        // ---- compute on stage c&1
        const uint32_t stb = sbase + (c & 1) * STAGE_BYTES;
        const uint32_t bAh = stb;
        const uint32_t bAl = stb + TILE_BYTES;
        const uint32_t bBh = stb + 2 * TILE_BYTES;
        const uint32_t bBl = stb + 3 * TILE_BYTES;

        #pragma unroll
        for (int kk = 0; kk < 2; kk++) {
            const int ko = kk * 16 + (lane >> 4) * 8;   // half offset within row
            uint32_t a_h[2][4], a_l[2][4];
            const int ar = wm * 32 + (lane & 15);
            #pragma unroll
            for (int mt = 0; mt < 2; mt++) {
                ldm_x4(a_h[mt], bAh + ((ar + mt * 16) * LDK + ko) * 2);
                ldm_x4(a_l[mt], bAl + ((ar + mt * 16) * LDK + ko) * 2);
            }
            uint32_t b_h[8][2], b_l[8][2];
            #pragma unroll
            for (int nt2 = 0; nt2 < 4; nt2++) {
                const int br = wn * 64 + nt2 * 16 + (lane & 15);
                uint32_t r[4];
                ldm_x4(r, bBh + (br * LDK + ko) * 2);
                b_h[nt2 * 2][0] = r[0]; b_h[nt2 * 2 + 1][0] = r[1];
                b_h[nt2 * 2][1] = r[2]; b_h[nt2 * 2 + 1][1] = r[3];
                ldm_x4(r, bBl + (br * LDK + ko) * 2);
                b_l[nt2 * 2][0] = r[0]; b_l[nt2 * 2 + 1][0] = r[1];
                b_l[nt2 * 2][1] = r[2]; b_l[nt2 * 2 + 1][1] = r[3];
            }
            #pragma unroll
            for (int mt = 0; mt < 2; mt++)
                #pragma unroll
                for (int nt = 0; nt < 8; nt++) {
                    mma16816(acc[mt][nt], a_h[mt], b_h[nt]);
                    mma16816(acc[mt][nt], a_h[mt], b_l[nt]);
                    mma16816(acc[mt][nt], a_l[mt], b_h[nt]);
                }
        }
        __syncthreads();
    }

    // ---- epilogue: direct fp32 stores
    float* outb = outp + (size_t)b * Mdim * P_;
    #pragma unroll
    for (int mt = 0; mt < 2; mt++) {
        int r1 = m0 + wm * 32 + mt * 16 + (lane >> 2);
        #pragma unroll
        for (int nt = 0; nt < 8; nt++) {
            int col = n0 + wn * 64 + nt * 8 + 2 * (lane & 3);
            float2 v0 = make_float2(acc[mt][nt][0], acc[mt][nt][1]);
            float2 v1 = make_float2(acc[mt][nt][2], acc[mt][nt][3]);
            *(float2*)&outb[(size_t)r1 * P_ + col]       = v0;
            *(float2*)&outb[(size_t)(r1 + 8) * P_ + col] = v1;
        }
    }
}

// ---------------------------------------------------------------------------
// Depthwise 3x3 conv (pad 1) + exact GELU on bs channels, per batch
// grid (HH/16, CT), 256 threads
// ---------------------------------------------------------------------------
__global__ __launch_bounds__(256) void dw_kernel(
    const float* __restrict__ w_dw,
    const float* __restrict__ w_bs_dw, int b)
{
    __shared__ float s[18][128];
    const int y0 = blockIdx.x * 16;
    const int ch = blockIdx.y;
    const int tid = threadIdx.x;

    const float* in = g_pw + ((size_t)b * CT_ + ch) * P_;
    #pragma unroll
    for (int e = 0; e < 9; e++) {
        int idx = tid + e * 256;
        int row = idx >> 7, col = idx & 127;
        int y = y0 - 1 + row;
        s[row][col] = (y >= 0 && y < HH_) ? in[y * WW_ + col] : 0.f;
    }
    __syncthreads();

    const float* wp = (ch < C3_) ? (w_dw + ch * 9) : (w_bs_dw + (ch - C3_) * 9);
    float w[9];
    #pragma unroll
    for (int i = 0; i < 9; i++) w[i] = __ldg(&wp[i]);

    float* outc = g_dw + ((size_t)b * CT_ + ch) * P_;
    const int x = tid & 127;
    #pragma unroll
    for (int i = 0; i < 8; i++) {
        int r = 2 * i + (tid >> 7);
        const float* s0 = s[r];
        const float* s1 = s[r + 1];
        const float* s2 = s[r + 2];
        float acc = w[1] * s0[x] + w[4] * s1[x] + w[7] * s2[x];
        if (x > 0)
            acc += w[0] * s0[x - 1] + w[3] * s1[x - 1] + w[6] * s2[x - 1];
        if (x < 127)
            acc += w[2] * s0[x + 1] + w[5] * s1[x + 1] + w[8] * s2[x + 1];
        if (ch >= C3_)
            acc = 0.5f * acc * (1.0f + erff(acc * 0.70710678118654752f));
        outc[(y0 + r) * WW_ + x] = acc;
    }
}

// ---------------------------------------------------------------------------
// L2 norms of q and k rows (per batch): grid 2*C_ blocks
// ---------------------------------------------------------------------------
__global__ __launch_bounds__(256) void norm_kernel(int b)
{
    const int bid = blockIdx.x;           // 0..767
    const int isk = bid >= C_;
    const int c   = isk ? bid - C_ : bid;
    const float* src = g_dw + ((size_t)b * CT_ + (isk ? C_ + c : c)) * P_;

    float s = 0.f;
    for (int i = threadIdx.x; i < P_; i += 256) {
        float t = src[i];
        s += t * t;
    }
    __shared__ float red[256];
    red[threadIdx.x] = s;
    __syncthreads();
    for (int off = 128; off > 0; off >>= 1) {
        if (threadIdx.x < off) red[threadIdx.x] += red[threadIdx.x + off];
        __syncthreads();
    }
    if (threadIdx.x == 0)
        g_norms[(isk ? B_ * C_ : 0) + b * C_ + c] = fmaxf(sqrtf(red[0]), 1e-12f);
}

// ---------------------------------------------------------------------------
// Attention logits split-K partials (f32x2), per batch: grid (SPLITS, HEADS)
// ---------------------------------------------------------------------------
__global__ __launch_bounds__(256) void attn_part_kernel(int b)
{
    const int s = blockIdx.x;   // 0..15
    const int h = blockIdx.y;   // 0..7
    const int bh = b * HEADS_ + h;

    const float* qb = g_dw + ((size_t)b * CT_ + h * CH_) * P_ + s * 1024;
    const float* kb = g_dw + ((size_t)b * CT_ + C_ + h * CH_) * P_ + s * 1024;

    __shared__ __align__(16) float qs[48][66];
    __shared__ __align__(16) float ks[48][66];

    const int tid = threadIdx.x;
    const int tx = tid & 15, ty = tid >> 4;
    const int i0 = ty * 3, j0 = tx * 3;
    unsigned long long acc[3][3];
    #pragma unroll
    for (int i = 0; i < 3; i++)
        #pragma unroll
        for (int jj = 0; jj < 3; jj++) acc[i][jj] = 0ull;

    for (int p0 = 0; p0 < 1024; p0 += 64) {
        #pragma unroll
        for (int e = 0; e < 12; e++) {
            int idx = tid + e * 256;
            int row = idx >> 6, col = idx & 63;
            qs[row][col] = qb[(size_t)row * P_ + p0 + col];
            ks[row][col] = kb[(size_t)row * P_ + p0 + col];
        }
        __syncthreads();
        #pragma unroll 8
        for (int p = 0; p < 64; p += 2) {
            unsigned long long a0 = __double_as_longlong(*(const double*)&qs[i0][p]);
            unsigned long long a1 = __double_as_longlong(*(const double*)&qs[i0 + 1][p]);
            unsigned long long a2 = __double_as_longlong(*(const double*)&qs[i0 + 2][p]);
            unsigned long long b0 = __double_as_longlong(*(const double*)&ks[j0][p]);
            unsigned long long b1 = __double_as_longlong(*(const double*)&ks[j0 + 1][p]);
            unsigned long long b2 = __double_as_longlong(*(const double*)&ks[j0 + 2][p]);
            fma_f32x2(acc[0][0], a0, b0); fma_f32x2(acc[0][1], a0, b1); fma_f32x2(acc[0][2], a0, b2);
            fma_f32x2(acc[1][0], a1, b0); fma_f32x2(acc[1][1], a1, b1); fma_f32x2(acc[1][2], a1, b2);
            fma_f32x2(acc[2][0], a2, b0); fma_f32x2(acc[2][1], a2, b1); fma_f32x2(acc[2][2], a2, b2);
        }
        __syncthreads();
    }

    float* out = g_part + ((size_t)bh * SPLITS_ + s) * (CH_ * CH_);
    #pragma unroll
    for (int i = 0; i < 3; i++)
        #pragma unroll
        for (int jj = 0; jj < 3; jj++)
            out[(i0 + i) * CH_ + j0 + jj] = f2lo(acc[i][jj]) + f2hi(acc[i][jj]);
}

// ---------------------------------------------------------------------------
// Softmax rows, per batch: grid (CH, HEADS)
// ---------------------------------------------------------------------------
__global__ __launch_bounds__(64) void softmax_kernel(int b)
{
    const int i = blockIdx.x;
    const int h = blockIdx.y;
    const int bh = b * HEADS_ + h;
    const int j = threadIdx.x;

    float val = 0.f;
    float logit = -1e30f;
    if (j < CH_) {
        float sum = 0.f;
        #pragma unroll
        for (int s = 0; s < SPLITS_; s++)
            sum += g_part[((size_t)bh * SPLITS_ + s) * (CH_ * CH_) + i * CH_ + j];
        float nq = g_norms[b * C_ + h * CH_ + i];
        float nk = g_norms[B_ * C_ + b * C_ + h * CH_ + j];
        val = sum / (nq * nk) * SCALE_;
        logit = val;
    }
    __shared__ float red[64];
    red[j] = logit;
    __syncthreads();
    for (int off = 32; off > 0; off >>= 1) {
        if (j < off) red[j] = fmaxf(red[j], red[j + off]);
        __syncthreads();
    }
    float mx = red[0];
    __syncthreads();
    float e = (j < CH_) ? expf(val - mx) : 0.f;
    red[j] = e;
    __syncthreads();
    for (int off = 32; off > 0; off >>= 1) {
        if (j < off) red[j] += red[j + off];
        __syncthreads();
    }
    if (j < CH_) g_attn[(size_t)bh * CH_ * CH_ + i * CH_ + j] = e / red[0];
}

// ---------------------------------------------------------------------------
// out = attn @ V, written directly as hi/lo fp16 into proj input cols 0..383
// per batch: grid (P/128, HEADS), 128 threads (one pixel each)
// ---------------------------------------------------------------------------
__global__ __launch_bounds__(128) void av_kernel(int b)
{
    const int pb = blockIdx.x;
    const int h  = blockIdx.y;
    const int bh = b * HEADS_ + h;
    const int p = pb * 128 + threadIdx.x;

    __shared__ float at[CH_ * CH_];
    for (int idx = threadIdx.x; idx < CH_ * CH_; idx += 128)
        at[idx] = g_attn[(size_t)bh * CH_ * CH_ + idx];
    __syncthreads();

    const float* vb = g_dw + ((size_t)b * CT_ + 2 * C_ + h * CH_) * P_ + p;
    float v[CH_];
    #pragma unroll
    for (int d = 0; d < CH_; d++) v[d] = vb[(size_t)d * P_];

    uint32_t hb[24], lb[24];
    #pragma unroll 4
    for (int cp = 0; cp < 24; cp++) {
        float a0 = 0.f, a1 = 0.f;
        #pragma unroll
        for (int d = 0; d < CH_; d++) {
            a0 += at[(2 * cp) * CH_ + d] * v[d];
            a1 += at[(2 * cp + 1) * CH_ + d] * v[d];
        }
        __half h0, l0, h1, l1;
        split_h(a0, h0, l0); split_h(a1, h1, l1);
        hb[cp] = pack_h(h0, h1); lb[cp] = pack_h(l0, l1);
    }

    size_t base = ((size_t)b * P_ + p) * (2 * C_) + h * CH_;
    uint4* dh = (uint4*)&g_pT_h[base];
    uint4* dl = (uint4*)&g_pT_l[base];
    #pragma unroll
    for (int q = 0; q < 6; q++) {
        dh[q] = *(uint4*)&hb[q * 4];
        dl[q] = *(uint4*)&lb[q * 4];
    }
}

// ---------------------------------------------------------------------------
extern "C" void kernel_launch(void* const* d_in, const int* in_sizes, int n_in,
                              void* d_out, int out_size)
{
    const float* x       = (const float*)d_in[0];
    const float* w_qkv   = (const float*)d_in[1];
    const float* w_dw    = (const float*)d_in[2];
    const float* w_proj  = (const float*)d_in[3];
    const float* w_bs_pw = (const float*)d_in[4];
    const float* w_bs_dw = (const float*)d_in[5];
    float* out = (float*)d_out;

    // One-time infra: second stream + fork/join events (host objects, no
    // device allocation). Created on the first (non-captured) call.
    static cudaStream_t sB = nullptr;
    static cudaEvent_t evPw[B_], evChain[B_];
    if (sB == nullptr) {
        cudaStreamCreateWithFlags(&sB, cudaStreamNonBlocking);
        for (int b = 0; b < B_; b++) {
            cudaEventCreateWithFlags(&evPw[b], cudaEventDisableTiming);
            cudaEventCreateWithFlags(&evChain[b], cudaEventDisableTiming);
        }
        cudaFuncSetAttribute(gemm_mma_kernel<0>,
                             cudaFuncAttributeMaxDynamicSharedMemorySize, GEMM_SMEM);
        cudaFuncSetAttribute(gemm_mma_kernel<1>,
                             cudaFuncAttributeMaxDynamicSharedMemorySize, GEMM_SMEM);
    }

    float* pw = nullptr;
    cudaGetSymbolAddress((void**)&pw, g_pw);

    // Prologue on main stream: weight convert + x transpose/convert (all batches)
    {
        int total = CT_ * C_ + C_ * 2 * C_;
        conv_w_kernel<<<(total + 255) / 256, 256>>>(w_qkv, w_bs_pw, w_proj);
    }
    pack_x_kernel<<<dim3(P_ / 64, C_ / 96, B_), 256>>>(x);

    // Stream A (main): pw GEMMs back-to-back (tensor-bound).
    // Stream B: per-batch memory chain as soon as its pw finishes.
    for (int b = 0; b < B_; b++) {
        gemm_mma_kernel<0><<<dim3(P_ / 128, CT_ / 128), 256, GEMM_SMEM>>>(pw, b);
        cudaEventRecord(evPw[b], 0);

        cudaStreamWaitEvent(sB, evPw[b], 0);
        dw_kernel<<<dim3(HH_ / 16, CT_), 256, 0, sB>>>(w_dw, w_bs_dw, b);
        norm_kernel<<<2 * C_, 256, 0, sB>>>(b);
        attn_part_kernel<<<dim3(SPLITS_, HEADS_), 256, 0, sB>>>(b);
        softmax_kernel<<<dim3(CH_, HEADS_), 64, 0, sB>>>(b);
        av_kernel<<<dim3(P_ / 128, HEADS_), 128, 0, sB>>>(b);
        pack_proj_kernel<<<dim3(P_ / 64, C_ / 96), 256, 0, sB>>>(b);
        cudaEventRecord(evChain[b], sB);
    }

    // Stream A: proj GEMMs (each waits for its batch's chain)
    for (int b = 0; b < B_; b++) {
        cudaStreamWaitEvent(0, evChain[b], 0);
        gemm_mma_kernel<1><<<dim3(P_ / 128, C_ / 128), 256, GEMM_SMEM>>>(out, b);
    }
}

// round 7
// speedup vs baseline: 2.6925x; 1.4120x over previous
#include <cuda_runtime.h>
#include <cuda_fp16.h>
#include <math.h>
#include <stdint.h>

// Problem constants
#define B_    4
#define C_    384
#define C3_   1152
#define CT_   1536        // 1152 qkv + 384 bs
#define HH_   128
#define WW_   128
#define P_    16384       // H*W
#define HEADS_ 8
#define CH_   48
#define BH_   32          // B*HEADS
#define SPLITS_ 16
#define SCALE_ 0.14433756729740643f  // 1/sqrt(48)

#define LDK 40            // padded K stride (halfs) in GEMM smem tiles

// Scratch (static device arrays; no cudaMalloc allowed)
__device__ float g_pw[(size_t)B_ * CT_ * P_];       // pointwise output (fp32)
__device__ float g_dw[(size_t)B_ * CT_ * P_];       // depthwise output (q,k,v,y)
__device__ float g_part[(size_t)BH_ * SPLITS_ * CH_ * CH_];
__device__ float g_norms[2 * B_ * C_];              // q norms then k norms
__device__ float g_npart[(size_t)B_ * 2 * C_ * 8];  // per-block sumsq partials
__device__ float g_attn[(size_t)BH_ * CH_ * CH_];
// weights: exact hi/lo fp16 split (2-term GEMM); activations: single fp16
__device__ __align__(256) __half g_wA_h[(size_t)CT_ * C_];      // [m][k]
__device__ __align__(256) __half g_wA_l[(size_t)CT_ * C_];
__device__ __align__(256) __half g_wP_h[(size_t)C_ * 2 * C_];
__device__ __align__(256) __half g_wP_l[(size_t)C_ * 2 * C_];
__device__ __align__(256) __half g_xT[(size_t)B_ * P_ * C_];    // [b][p][k]
__device__ __align__(256) __half g_pT[(size_t)B_ * P_ * 2 * C_];

// ---------------------------------------------------------------------------
// Helpers
// ---------------------------------------------------------------------------
__device__ __forceinline__ uint32_t smem_u32(const void* p) {
    uint32_t a;
    asm("{ .reg .u64 t; cvta.to.shared.u64 t, %1; cvt.u32.u64 %0, t; }"
        : "=r"(a) : "l"(p));
    return a;
}
__device__ __forceinline__ void cp16(uint32_t sa, const void* g) {
    asm volatile("cp.async.cg.shared.global [%0], [%1], 16;" :: "r"(sa), "l"(g));
}
#define CP_COMMIT() asm volatile("cp.async.commit_group;" ::: "memory")
#define CP_WAIT0()  asm volatile("cp.async.wait_group 0;" ::: "memory")

__device__ __forceinline__ void ldm_x4(uint32_t* r, uint32_t addr) {
    asm volatile("ldmatrix.sync.aligned.m8n8.x4.shared.b16 {%0,%1,%2,%3}, [%4];"
        : "=r"(r[0]), "=r"(r[1]), "=r"(r[2]), "=r"(r[3]) : "r"(addr));
}
__device__ __forceinline__ void mma16816(float* c, const uint32_t* a, const uint32_t* b) {
    asm volatile("mma.sync.aligned.m16n8k16.row.col.f32.f16.f16.f32 "
        "{%0,%1,%2,%3}, {%4,%5,%6,%7}, {%8,%9}, {%0,%1,%2,%3};"
        : "+f"(c[0]), "+f"(c[1]), "+f"(c[2]), "+f"(c[3])
        : "r"(a[0]), "r"(a[1]), "r"(a[2]), "r"(a[3]), "r"(b[0]), "r"(b[1]));
}

// f32x2 helpers (FFMA2)
__device__ __forceinline__ void fma_f32x2(unsigned long long& d,
                                          unsigned long long a,
                                          unsigned long long b) {
    asm("fma.rn.f32x2 %0, %1, %2, %0;" : "+l"(d) : "l"(a), "l"(b));
}
__device__ __forceinline__ float f2lo(unsigned long long v) {
    return __uint_as_float((unsigned)v);
}
__device__ __forceinline__ float f2hi(unsigned long long v) {
    return __uint_as_float((unsigned)(v >> 32));
}

__device__ __forceinline__ void split_h(float v, __half& h, __half& l) {
    h = __float2half(v);
    l = __float2half(v - __half2float(h));
}
__device__ __forceinline__ uint32_t pack_h(__half a, __half b) {
    return (uint32_t)__half_as_ushort(a) | ((uint32_t)__half_as_ushort(b) << 16);
}

// ---------------------------------------------------------------------------
// Weight convert: hi/lo fp16, native [m][k] layout
// ---------------------------------------------------------------------------
__global__ __launch_bounds__(256) void conv_w_kernel(
    const float* __restrict__ w_qkv,
    const float* __restrict__ w_bs_pw,
    const float* __restrict__ w_proj)
{
    const int nA = CT_ * C_;       // 589824
    const int nP = C_ * 2 * C_;    // 294912
    int idx = blockIdx.x * 256 + threadIdx.x;
    if (idx < nA) {
        int m = idx / C_, k = idx % C_;
        float v = (m < C3_) ? w_qkv[m * C_ + k] : w_bs_pw[(m - C3_) * C_ + k];
        __half h, l; split_h(v, h, l);
        g_wA_h[idx] = h; g_wA_l[idx] = l;
    } else if (idx < nA + nP) {
        int j = idx - nA;
        float v = w_proj[j];
        __half h, l; split_h(v, h, l);
        g_wP_h[j] = h; g_wP_l[j] = l;
    }
}

// ---------------------------------------------------------------------------
// Transpose+convert x: [b][c][p] fp32 -> [b][p][c] fp16 (single)
// grid (P/64, C/96, B), 256 threads
// ---------------------------------------------------------------------------
__global__ __launch_bounds__(256) void pack_x_kernel(const float* __restrict__ x)
{
    __shared__ __align__(16) float s[96][68];
    const int p0  = blockIdx.x * 64;
    const int ci0 = blockIdx.y * 96;
    const int b   = blockIdx.z;
    const int tid = threadIdx.x;

    #pragma unroll
    for (int e = 0; e < 24; e++) {
        int idx = tid + e * 256;
        int row = idx >> 6, col = idx & 63;
        s[row][col] = x[((size_t)b * C_ + ci0 + row) * P_ + p0 + col];
    }
    __syncthreads();

    const int px = tid & 63, part = tid >> 6;       // 4 parts x 24 ch
    size_t base = ((size_t)b * P_ + p0 + px) * C_ + ci0 + part * 24;
    uint32_t hb[12];
    #pragma unroll
    for (int k = 0; k < 12; k++) {
        __half h0 = __float2half(s[part * 24 + 2 * k][px]);
        __half h1 = __float2half(s[part * 24 + 2 * k + 1][px]);
        hb[k] = pack_h(h0, h1);
    }
    uint4* dh = (uint4*)&g_xT[base];
    #pragma unroll
    for (int q = 0; q < 3; q++) dh[q] = *(uint4*)&hb[q * 4];
}

// ---------------------------------------------------------------------------
// Transpose+convert y (bs branch) into proj input cols 384..767
// grid (P/64, 384/96, B), 256 threads
// ---------------------------------------------------------------------------
__global__ __launch_bounds__(256) void pack_proj_kernel()
{
    __shared__ __align__(16) float s[96][68];
    const int p0  = blockIdx.x * 64;
    const int ci0 = blockIdx.y * 96;
    const int b   = blockIdx.z;
    const int tid = threadIdx.x;

    #pragma unroll
    for (int e = 0; e < 24; e++) {
        int idx = tid + e * 256;
        int row = idx >> 6, col = idx & 63;
        s[row][col] = g_dw[((size_t)b * CT_ + C3_ + ci0 + row) * P_ + p0 + col];
    }
    __syncthreads();

    const int px = tid & 63, part = tid >> 6;
    size_t base = ((size_t)b * P_ + p0 + px) * (2 * C_) + C_ + ci0 + part * 24;
    uint32_t hb[12];
    #pragma unroll
    for (int k = 0; k < 12; k++) {
        __half h0 = __float2half(s[part * 24 + 2 * k][px]);
        __half h1 = __float2half(s[part * 24 + 2 * k + 1][px]);
        hb[k] = pack_h(h0, h1);
    }
    uint4* dh = (uint4*)&g_pT[base];
    #pragma unroll
    for (int q = 0; q < 3; q++) dh[q] = *(uint4*)&hb[q * 4];
}

// ---------------------------------------------------------------------------
// HMMA GEMM, 2-term weight split: D[M,N] = (Ah+Al)[M,K] @ B[N,K]^T (fp32 acc)
// CTA tile 128x128x32, 256 threads (8 warps = 4m x 2n, 32x64 each),
// cp.async double-buffered, smem = {Ah, Al, B} per stage.
// MODE 0: pw  (M=1536, K=384, out=g_pw); MODE 1: proj (M=384, K=768, out)
// ---------------------------------------------------------------------------
#define TILE_BYTES (128 * LDK * 2)          // 10240
#define STAGE_BYTES (3 * TILE_BYTES)        // Ah, Al, B = 30720
#define GEMM_SMEM (2 * STAGE_BYTES)         // 61440

template <int MODE>
__global__ __launch_bounds__(256) void gemm_mma_kernel(float* __restrict__ outp)
{
    extern __shared__ __align__(16) char S[];
    const int Kdim = (MODE == 0) ? C_ : 2 * C_;
    const int Mdim = (MODE == 0) ? CT_ : C_;
    const int b  = blockIdx.z;
    const int n0 = blockIdx.x * 128;
    const int m0 = blockIdx.y * 128;

    const __half* Ah = (MODE == 0) ? g_wA_h : g_wP_h;
    const __half* Al = (MODE == 0) ? g_wA_l : g_wP_l;
    const __half* Bp = ((MODE == 0) ? g_xT : g_pT) + (size_t)b * P_ * Kdim;

    const int tid  = threadIdx.x;
    const int lane = tid & 31, warp = tid >> 5;
    const int wm = warp >> 1, wn = warp & 1;
    const uint32_t sbase = smem_u32(S);

    float acc[2][8][4];
    #pragma unroll
    for (int mt = 0; mt < 2; mt++)
        #pragma unroll
        for (int nt = 0; nt < 8; nt++)
            #pragma unroll
            for (int q = 0; q < 4; q++) acc[mt][nt][q] = 0.f;

    const int nch = Kdim / 32;

    // ---- prologue load (stage 0, chunk 0): 3 tiles x 512 16B-chunks
    {
        const __half* gp[3] = { Ah + (size_t)m0 * Kdim, Al + (size_t)m0 * Kdim,
                                Bp + (size_t)n0 * Kdim };
        #pragma unroll
        for (int e = 0; e < 6; e++) {
            int idx = tid + e * 256;
            int t  = idx >> 9;
            int j2 = idx & 511;
            int r  = j2 >> 2;
            int sg = j2 & 3;
            uint32_t sa = sbase + t * TILE_BYTES + (r * LDK + sg * 8) * 2;
            cp16(sa, gp[t] + (size_t)r * Kdim + sg * 8);
        }
        CP_COMMIT();
    }

    for (int c = 0; c < nch; c++) {
        CP_WAIT0();
        __syncthreads();

        if (c + 1 < nch) {
            int k0 = (c + 1) * 32;
            int st = (c + 1) & 1;
            const __half* gp[3] = { Ah + (size_t)m0 * Kdim, Al + (size_t)m0 * Kdim,
                                    Bp + (size_t)n0 * Kdim };
            #pragma unroll
            for (int e = 0; e < 6; e++) {
                int idx = tid + e * 256;
                int t  = idx >> 9;
                int j2 = idx & 511;
                int r  = j2 >> 2;
                int sg = j2 & 3;
                uint32_t sa = sbase + st * STAGE_BYTES + t * TILE_BYTES
                            + (r * LDK + sg * 8) * 2;
                cp16(sa, gp[t] + (size_t)r * Kdim + k0 + sg * 8);
            }
            CP_COMMIT();
        }

        // ---- compute on stage c&1
        const uint32_t stb = sbase + (c & 1) * STAGE_BYTES;
        const uint32_t bAh = stb;
        const uint32_t bAl = stb + TILE_BYTES;
        const uint32_t bB  = stb + 2 * TILE_BYTES;

        #pragma unroll
        for (int kk = 0; kk < 2; kk++) {
            const int ko = kk * 16 + (lane >> 4) * 8;   // half offset within row
            const int ar = wm * 32 + (lane & 15);
            uint32_t a_h[2][4], a_l[2][4];
            #pragma unroll
            for (int mt = 0; mt < 2; mt++) {
                ldm_x4(a_h[mt], bAh + ((ar + mt * 16) * LDK + ko) * 2);
                ldm_x4(a_l[mt], bAl + ((ar + mt * 16) * LDK + ko) * 2);
            }
            uint32_t bmat[8][2];
            #pragma unroll
            for (int nt2 = 0; nt2 < 4; nt2++) {
                const int br = wn * 64 + nt2 * 16 + (lane & 15);
                uint32_t r[4];
                ldm_x4(r, bB + (br * LDK + ko) * 2);
                bmat[nt2 * 2][0] = r[0]; bmat[nt2 * 2 + 1][0] = r[1];
                bmat[nt2 * 2][1] = r[2]; bmat[nt2 * 2 + 1][1] = r[3];
            }
            #pragma unroll
            for (int mt = 0; mt < 2; mt++)
                #pragma unroll
                for (int nt = 0; nt < 8; nt++) {
                    mma16816(acc[mt][nt], a_h[mt], bmat[nt]);
                    mma16816(acc[mt][nt], a_l[mt], bmat[nt]);
                }
        }
        __syncthreads();
    }

    // ---- epilogue: direct fp32 stores
    float* outb = outp + (size_t)b * Mdim * P_;
    #pragma unroll
    for (int mt = 0; mt < 2; mt++) {
        int r1 = m0 + wm * 32 + mt * 16 + (lane >> 2);
        #pragma unroll
        for (int nt = 0; nt < 8; nt++) {
            int col = n0 + wn * 64 + nt * 8 + 2 * (lane & 3);
            float2 v0 = make_float2(acc[mt][nt][0], acc[mt][nt][1]);
            float2 v1 = make_float2(acc[mt][nt][2], acc[mt][nt][3]);
            *(float2*)&outb[(size_t)r1 * P_ + col]       = v0;
            *(float2*)&outb[(size_t)(r1 + 8) * P_ + col] = v1;
        }
    }
}

// ---------------------------------------------------------------------------
// Depthwise 3x3 conv (pad 1) + exact GELU on bs channels, rolling-window,
// fused q/k sum-of-squares partials. grid (HH/16, CT, B), 256 threads.
// ---------------------------------------------------------------------------
__global__ __launch_bounds__(256) void dw_kernel(
    const float* __restrict__ w_dw,
    const float* __restrict__ w_bs_dw)
{
    __shared__ float s[18][132];
    __shared__ float red[8];
    const int y0 = blockIdx.x * 16;
    const int ch = blockIdx.y;
    const int b  = blockIdx.z;
    const int tid = threadIdx.x;

    const float* in = g_pw + ((size_t)b * CT_ + ch) * P_;
    #pragma unroll
    for (int e = 0; e < 9; e++) {
        int idx = tid + e * 256;
        int row = idx >> 7, col = idx & 127;
        int y = y0 - 1 + row;
        s[row][col + 1] = (y >= 0 && y < HH_) ? in[y * WW_ + col] : 0.f;
    }
    if (tid < 36) s[tid >> 1][(tid & 1) * 129] = 0.f;
    __syncthreads();

    const float* wp = (ch < C3_) ? (w_dw + ch * 9) : (w_bs_dw + (ch - C3_) * 9);
    float w[9];
    #pragma unroll
    for (int i = 0; i < 9; i++) w[i] = __ldg(&wp[i]);

    float* outc = g_dw + ((size_t)b * CT_ + ch) * P_;
    const int x = tid & 127;
    const int g = tid >> 7;            // 0 or 1: rows g*8 .. g*8+7
    const int rb = g * 8;

    float l0 = s[rb][x],     m0 = s[rb][x + 1],     r0 = s[rb][x + 2];
    float l1 = s[rb + 1][x], m1 = s[rb + 1][x + 1], r1 = s[rb + 1][x + 2];
    float sumsq = 0.f;

    #pragma unroll
    for (int j = 0; j < 8; j++) {
        float l2 = s[rb + j + 2][x];
        float m2 = s[rb + j + 2][x + 1];
        float r2 = s[rb + j + 2][x + 2];
        float acc = w[0] * l0 + w[1] * m0 + w[2] * r0
                  + w[3] * l1 + w[4] * m1 + w[5] * r1
                  + w[6] * l2 + w[7] * m2 + w[8] * r2;
        if (ch >= C3_)
            acc = 0.5f * acc * (1.0f + erff(acc * 0.70710678118654752f));
        outc[(y0 + rb + j) * WW_ + x] = acc;
        sumsq += acc * acc;
        l0 = l1; m0 = m1; r0 = r1;
        l1 = l2; m1 = m2; r1 = r2;
    }

    // fused q/k norm partials (channels 0..2C-1)
    if (ch < 2 * C_) {
        #pragma unroll
        for (int off = 16; off > 0; off >>= 1)
            sumsq += __shfl_xor_sync(0xFFFFFFFFu, sumsq, off);
        if ((tid & 31) == 0) red[tid >> 5] = sumsq;
        __syncthreads();
        if (tid == 0) {
            float t = red[0];
            #pragma unroll
            for (int q = 1; q < 8; q++) t += red[q];
            g_npart[(((size_t)b * 2 * C_ + ch) << 3) + blockIdx.x] = t;
        }
    }
}

// ---------------------------------------------------------------------------
// Finalize norms: one thread per (b, ch) over 8 partials
// grid (B*2C/256), 256 threads
// ---------------------------------------------------------------------------
__global__ __launch_bounds__(256) void norm_fin_kernel()
{
    int idx = blockIdx.x * 256 + threadIdx.x;      // 0 .. B*768-1
    if (idx >= B_ * 2 * C_) return;
    int b = idx / (2 * C_), ch = idx % (2 * C_);
    const float* p = g_npart + ((size_t)idx << 3);
    float t = 0.f;
    #pragma unroll
    for (int q = 0; q < 8; q++) t += p[q];
    float nv = fmaxf(sqrtf(t), 1e-12f);
    if (ch < C_) g_norms[b * C_ + ch] = nv;
    else         g_norms[B_ * C_ + b * C_ + (ch - C_)] = nv;
}

// ---------------------------------------------------------------------------
// Attention logits split-K partials (f32x2)
// ---------------------------------------------------------------------------
__global__ __launch_bounds__(256) void attn_part_kernel()
{
    const int s  = blockIdx.x;   // 0..15
    const int bh = blockIdx.y;   // 0..31
    const int b = bh >> 3, h = bh & 7;

    const float* qb = g_dw + ((size_t)b * CT_ + h * CH_) * P_ + s * 1024;
    const float* kb = g_dw + ((size_t)b * CT_ + C_ + h * CH_) * P_ + s * 1024;

    __shared__ __align__(16) float qs[48][66];
    __shared__ __align__(16) float ks[48][66];

    const int tid = threadIdx.x;
    const int tx = tid & 15, ty = tid >> 4;
    const int i0 = ty * 3, j0 = tx * 3;
    unsigned long long acc[3][3];
    #pragma unroll
    for (int i = 0; i < 3; i++)
        #pragma unroll
        for (int jj = 0; jj < 3; jj++) acc[i][jj] = 0ull;

    for (int p0 = 0; p0 < 1024; p0 += 64) {
        #pragma unroll
        for (int e = 0; e < 12; e++) {
            int idx = tid + e * 256;
            int row = idx >> 6, col = idx & 63;
            qs[row][col] = qb[(size_t)row * P_ + p0 + col];
            ks[row][col] = kb[(size_t)row * P_ + p0 + col];
        }
        __syncthreads();
        #pragma unroll 8
        for (int p = 0; p < 64; p += 2) {
            unsigned long long a0 = __double_as_longlong(*(const double*)&qs[i0][p]);
            unsigned long long a1 = __double_as_longlong(*(const double*)&qs[i0 + 1][p]);
            unsigned long long a2 = __double_as_longlong(*(const double*)&qs[i0 + 2][p]);
            unsigned long long b0 = __double_as_longlong(*(const double*)&ks[j0][p]);
            unsigned long long b1 = __double_as_longlong(*(const double*)&ks[j0 + 1][p]);
            unsigned long long b2 = __double_as_longlong(*(const double*)&ks[j0 + 2][p]);
            fma_f32x2(acc[0][0], a0, b0); fma_f32x2(acc[0][1], a0, b1); fma_f32x2(acc[0][2], a0, b2);
            fma_f32x2(acc[1][0], a1, b0); fma_f32x2(acc[1][1], a1, b1); fma_f32x2(acc[1][2], a1, b2);
            fma_f32x2(acc[2][0], a2, b0); fma_f32x2(acc[2][1], a2, b1); fma_f32x2(acc[2][2], a2, b2);
        }
        __syncthreads();
    }

    float* out = g_part + ((size_t)bh * SPLITS_ + s) * (CH_ * CH_);
    #pragma unroll
    for (int i = 0; i < 3; i++)
        #pragma unroll
        for (int jj = 0; jj < 3; jj++)
            out[(i0 + i) * CH_ + j0 + jj] = f2lo(acc[i][jj]) + f2hi(acc[i][jj]);
}

// ---------------------------------------------------------------------------
// Softmax rows (with normalization by q/k norms and scale)
// ---------------------------------------------------------------------------
__global__ __launch_bounds__(64) void softmax_kernel()
{
    const int i  = blockIdx.x;
    const int bh = blockIdx.y;
    const int b = bh >> 3, h = bh & 7;
    const int j = threadIdx.x;

    float val = 0.f;
    float logit = -1e30f;
    if (j < CH_) {
        float sum = 0.f;
        #pragma unroll
        for (int s = 0; s < SPLITS_; s++)
            sum += g_part[((size_t)bh * SPLITS_ + s) * (CH_ * CH_) + i * CH_ + j];
        float nq = g_norms[b * C_ + h * CH_ + i];
        float nk = g_norms[B_ * C_ + b * C_ + h * CH_ + j];
        val = sum / (nq * nk) * SCALE_;
        logit = val;
    }
    __shared__ float red[64];
    red[j] = logit;
    __syncthreads();
    for (int off = 32; off > 0; off >>= 1) {
        if (j < off) red[j] = fmaxf(red[j], red[j + off]);
        __syncthreads();
    }
    float mx = red[0];
    __syncthreads();
    float e = (j < CH_) ? expf(val - mx) : 0.f;
    red[j] = e;
    __syncthreads();
    for (int off = 32; off > 0; off >>= 1) {
        if (j < off) red[j] += red[j + off];
        __syncthreads();
    }
    if (j < CH_) g_attn[(size_t)bh * CH_ * CH_ + i * CH_ + j] = e / red[0];
}

// ---------------------------------------------------------------------------
// out = attn @ V, written directly as fp16 into proj input cols 0..383
// grid (P/128, BH), 128 threads (one pixel each)
// ---------------------------------------------------------------------------
__global__ __launch_bounds__(128) void av_kernel()
{
    const int pb = blockIdx.x;
    const int bh = blockIdx.y;
    const int b = bh >> 3, h = bh & 7;
    const int p = pb * 128 + threadIdx.x;

    __shared__ float at[CH_ * CH_];
    for (int idx = threadIdx.x; idx < CH_ * CH_; idx += 128)
        at[idx] = g_attn[(size_t)bh * CH_ * CH_ + idx];
    __syncthreads();

    const float* vb = g_dw + ((size_t)b * CT_ + 2 * C_ + h * CH_) * P_ + p;
    float v[CH_];
    #pragma unroll
    for (int d = 0; d < CH_; d++) v[d] = vb[(size_t)d * P_];

    uint32_t hb[24];
    #pragma unroll 4
    for (int cp = 0; cp < 24; cp++) {
        float a0 = 0.f, a1 = 0.f;
        #pragma unroll
        for (int d = 0; d < CH_; d++) {
            a0 += at[(2 * cp) * CH_ + d] * v[d];
            a1 += at[(2 * cp + 1) * CH_ + d] * v[d];
        }
        hb[cp] = pack_h(__float2half(a0), __float2half(a1));
    }

    size_t base = ((size_t)b * P_ + p) * (2 * C_) + h * CH_;
    uint4* dh = (uint4*)&g_pT[base];
    #pragma unroll
    for (int q = 0; q < 6; q++) dh[q] = *(uint4*)&hb[q * 4];
}

// ---------------------------------------------------------------------------
extern "C" void kernel_launch(void* const* d_in, const int* in_sizes, int n_in,
                              void* d_out, int out_size)
{
    const float* x       = (const float*)d_in[0];
    const float* w_qkv   = (const float*)d_in[1];
    const float* w_dw    = (const float*)d_in[2];
    const float* w_proj  = (const float*)d_in[3];
    const float* w_bs_pw = (const float*)d_in[4];
    const float* w_bs_dw = (const float*)d_in[5];
    float* out = (float*)d_out;

    cudaFuncSetAttribute(gemm_mma_kernel<0>,
                         cudaFuncAttributeMaxDynamicSharedMemorySize, GEMM_SMEM);
    cudaFuncSetAttribute(gemm_mma_kernel<1>,
                         cudaFuncAttributeMaxDynamicSharedMemorySize, GEMM_SMEM);

    float* pw = nullptr;
    cudaGetSymbolAddress((void**)&pw, g_pw);

    // 0) weight convert + x transpose/convert
    {
        int total = CT_ * C_ + C_ * 2 * C_;
        conv_w_kernel<<<(total + 255) / 256, 256>>>(w_qkv, w_bs_pw, w_proj);
    }
    pack_x_kernel<<<dim3(P_ / 64, C_ / 96, B_), 256>>>(x);
    // 1) fused pointwise GEMM (HMMA 2-term weight split)
    gemm_mma_kernel<0><<<dim3(P_ / 128, CT_ / 128, B_), 256, GEMM_SMEM>>>(pw);
    // 2) depthwise 3x3 (+GELU on bs channels) with fused q/k sumsq partials
    dw_kernel<<<dim3(HH_ / 16, CT_, B_), 256>>>(w_dw, w_bs_dw);
    // 3) finalize q/k L2 norms
    norm_fin_kernel<<<(B_ * 2 * C_ + 255) / 256, 256>>>();
    // 4) attention logits (split-K partials, f32x2)
    attn_part_kernel<<<dim3(SPLITS_, BH_), 256>>>();
    // 5) softmax with normalization
    softmax_kernel<<<dim3(CH_, BH_), 64>>>();
    // 6) attn @ V -> proj input cols 0..383 (fp16)
    av_kernel<<<dim3(P_ / 128, BH_), 128>>>();
    // 6b) y branch -> proj input cols 384..767 (fp16)
    pack_proj_kernel<<<dim3(P_ / 64, C_ / 96, B_), 256>>>();
    // 7) projection GEMM -> output
    gemm_mma_kernel<1><<<dim3(P_ / 128, C_ / 128, B_), 256, GEMM_SMEM>>>(out);
}

// round 8
// speedup vs baseline: 3.5894x; 1.3331x over previous
#include <cuda_runtime.h>
#include <cuda_fp16.h>
#include <math.h>
#include <stdint.h>

// Problem constants
#define B_    4
#define C_    384
#define C3_   1152
#define CT_   1536        // 1152 qkv + 384 bs
#define HH_   128
#define WW_   128
#define P_    16384       // H*W
#define HEADS_ 8
#define CH_   48
#define BH_   32          // B*HEADS
#define SPLITS_ 16
#define SCALE_ 0.14433756729740643f  // 1/sqrt(48)

#define LDK 40            // padded K stride (halfs) in GEMM smem tiles

// Scratch (static device arrays; no cudaMalloc allowed)
__device__ float g_pw[(size_t)B_ * CT_ * P_];       // pointwise output (fp32)
__device__ float g_dw[(size_t)B_ * CT_ * P_];       // depthwise output (q,k,v,y)
__device__ float g_part[(size_t)BH_ * SPLITS_ * CH_ * CH_];
__device__ float g_norms[2 * B_ * C_];              // q norms then k norms
__device__ float g_npart[(size_t)B_ * 2 * C_ * 8];  // per-block sumsq partials
__device__ float g_attn[(size_t)BH_ * CH_ * CH_];
// fp16 operands (1-term GEMM)
__device__ __align__(256) __half g_wA[(size_t)CT_ * C_];      // [m][k]
__device__ __align__(256) __half g_wP[(size_t)C_ * 2 * C_];
__device__ __align__(256) __half g_xT[(size_t)B_ * P_ * C_];  // [b][p][k]
__device__ __align__(256) __half g_pT[(size_t)B_ * P_ * 2 * C_];

// ---------------------------------------------------------------------------
// Helpers
// ---------------------------------------------------------------------------
__device__ __forceinline__ uint32_t smem_u32(const void* p) {
    uint32_t a;
    asm("{ .reg .u64 t; cvta.to.shared.u64 t, %1; cvt.u32.u64 %0, t; }"
        : "=r"(a) : "l"(p));
    return a;
}
__device__ __forceinline__ void cp16(uint32_t sa, const void* g) {
    asm volatile("cp.async.cg.shared.global [%0], [%1], 16;" :: "r"(sa), "l"(g));
}
#define CP_COMMIT() asm volatile("cp.async.commit_group;" ::: "memory")
#define CP_WAIT0()  asm volatile("cp.async.wait_group 0;" ::: "memory")

__device__ __forceinline__ void ldm_x4(uint32_t* r, uint32_t addr) {
    asm volatile("ldmatrix.sync.aligned.m8n8.x4.shared.b16 {%0,%1,%2,%3}, [%4];"
        : "=r"(r[0]), "=r"(r[1]), "=r"(r[2]), "=r"(r[3]) : "r"(addr));
}
__device__ __forceinline__ void mma16816(float* c, const uint32_t* a, const uint32_t* b) {
    asm volatile("mma.sync.aligned.m16n8k16.row.col.f32.f16.f16.f32 "
        "{%0,%1,%2,%3}, {%4,%5,%6,%7}, {%8,%9}, {%0,%1,%2,%3};"
        : "+f"(c[0]), "+f"(c[1]), "+f"(c[2]), "+f"(c[3])
        : "r"(a[0]), "r"(a[1]), "r"(a[2]), "r"(a[3]), "r"(b[0]), "r"(b[1]));
}

// f32x2 helpers (FFMA2)
__device__ __forceinline__ void fma_f32x2(unsigned long long& d,
                                          unsigned long long a,
                                          unsigned long long b) {
    asm("fma.rn.f32x2 %0, %1, %2, %0;" : "+l"(d) : "l"(a), "l"(b));
}
__device__ __forceinline__ float f2lo(unsigned long long v) {
    return __uint_as_float((unsigned)v);
}
__device__ __forceinline__ float f2hi(unsigned long long v) {
    return __uint_as_float((unsigned)(v >> 32));
}

__device__ __forceinline__ uint32_t pack_h(__half a, __half b) {
    return (uint32_t)__half_as_ushort(a) | ((uint32_t)__half_as_ushort(b) << 16);
}

// ---------------------------------------------------------------------------
// Weight convert: fp16, native [m][k] layout
// ---------------------------------------------------------------------------
__global__ __launch_bounds__(256) void conv_w_kernel(
    const float* __restrict__ w_qkv,
    const float* __restrict__ w_bs_pw,
    const float* __restrict__ w_proj)
{
    const int nA = CT_ * C_;       // 589824
    const int nP = C_ * 2 * C_;    // 294912
    int idx = blockIdx.x * 256 + threadIdx.x;
    if (idx < nA) {
        int m = idx / C_, k = idx % C_;
        float v = (m < C3_) ? w_qkv[m * C_ + k] : w_bs_pw[(m - C3_) * C_ + k];
        g_wA[idx] = __float2half(v);
    } else if (idx < nA + nP) {
        int j = idx - nA;
        g_wP[j] = __float2half(w_proj[j]);
    }
}

// ---------------------------------------------------------------------------
// Transpose+convert x: [b][c][p] fp32 -> [b][p][c] fp16
// grid (P/64, C/96, B), 256 threads
// ---------------------------------------------------------------------------
__global__ __launch_bounds__(256) void pack_x_kernel(const float* __restrict__ x)
{
    __shared__ __align__(16) float s[96][68];
    const int p0  = blockIdx.x * 64;
    const int ci0 = blockIdx.y * 96;
    const int b   = blockIdx.z;
    const int tid = threadIdx.x;

    #pragma unroll
    for (int e = 0; e < 24; e++) {
        int idx = tid + e * 256;
        int row = idx >> 6, col = idx & 63;
        s[row][col] = x[((size_t)b * C_ + ci0 + row) * P_ + p0 + col];
    }
    __syncthreads();

    const int px = tid & 63, part = tid >> 6;       // 4 parts x 24 ch
    size_t base = ((size_t)b * P_ + p0 + px) * C_ + ci0 + part * 24;
    uint32_t hb[12];
    #pragma unroll
    for (int k = 0; k < 12; k++) {
        __half h0 = __float2half(s[part * 24 + 2 * k][px]);
        __half h1 = __float2half(s[part * 24 + 2 * k + 1][px]);
        hb[k] = pack_h(h0, h1);
    }
    uint4* dh = (uint4*)&g_xT[base];
    #pragma unroll
    for (int q = 0; q < 3; q++) dh[q] = *(uint4*)&hb[q * 4];
}

// ---------------------------------------------------------------------------
// Transpose+convert y (bs branch) into proj input cols 384..767
// grid (P/64, 384/96, B), 256 threads
// ---------------------------------------------------------------------------
__global__ __launch_bounds__(256) void pack_proj_kernel()
{
    __shared__ __align__(16) float s[96][68];
    const int p0  = blockIdx.x * 64;
    const int ci0 = blockIdx.y * 96;
    const int b   = blockIdx.z;
    const int tid = threadIdx.x;

    #pragma unroll
    for (int e = 0; e < 24; e++) {
        int idx = tid + e * 256;
        int row = idx >> 6, col = idx & 63;
        s[row][col] = g_dw[((size_t)b * CT_ + C3_ + ci0 + row) * P_ + p0 + col];
    }
    __syncthreads();

    const int px = tid & 63, part = tid >> 6;
    size_t base = ((size_t)b * P_ + p0 + px) * (2 * C_) + C_ + ci0 + part * 24;
    uint32_t hb[12];
    #pragma unroll
    for (int k = 0; k < 12; k++) {
        __half h0 = __float2half(s[part * 24 + 2 * k][px]);
        __half h1 = __float2half(s[part * 24 + 2 * k + 1][px]);
        hb[k] = pack_h(h0, h1);
    }
    uint4* dh = (uint4*)&g_pT[base];
    #pragma unroll
    for (int q = 0; q < 3; q++) dh[q] = *(uint4*)&hb[q * 4];
}

// ---------------------------------------------------------------------------
// HMMA GEMM, pure fp16: D[M,N] = A[M,K] @ B[N,K]^T (fp32 accum)
// CTA tile 128x128x32, 256 threads (8 warps = 4m x 2n, 32x64 each),
// cp.async double-buffered, smem = {A, B} per stage.
// MODE 0: pw  (M=1536, K=384, out=g_pw); MODE 1: proj (M=384, K=768, out)
// ---------------------------------------------------------------------------
#define TILE_BYTES (128 * LDK * 2)          // 10240
#define STAGE_BYTES (2 * TILE_BYTES)        // A, B = 20480
#define GEMM_SMEM (2 * STAGE_BYTES)         // 40960

template <int MODE>
__global__ __launch_bounds__(256) void gemm_mma_kernel(float* __restrict__ outp)
{
    extern __shared__ __align__(16) char S[];
    const int Kdim = (MODE == 0) ? C_ : 2 * C_;
    const int Mdim = (MODE == 0) ? CT_ : C_;
    const int b  = blockIdx.z;
    const int n0 = blockIdx.x * 128;
    const int m0 = blockIdx.y * 128;

    const __half* Ap = (MODE == 0) ? g_wA : g_wP;
    const __half* Bp = ((MODE == 0) ? g_xT : g_pT) + (size_t)b * P_ * Kdim;

    const int tid  = threadIdx.x;
    const int lane = tid & 31, warp = tid >> 5;
    const int wm = warp >> 1, wn = warp & 1;
    const uint32_t sbase = smem_u32(S);

    float acc[2][8][4];
    #pragma unroll
    for (int mt = 0; mt < 2; mt++)
        #pragma unroll
        for (int nt = 0; nt < 8; nt++)
            #pragma unroll
            for (int q = 0; q < 4; q++) acc[mt][nt][q] = 0.f;

    const int nch = Kdim / 32;

    // ---- prologue load (stage 0, chunk 0): 2 tiles x 512 16B-chunks
    {
        const __half* gp[2] = { Ap + (size_t)m0 * Kdim, Bp + (size_t)n0 * Kdim };
        #pragma unroll
        for (int e = 0; e < 4; e++) {
            int idx = tid + e * 256;
            int t  = idx >> 9;
            int j2 = idx & 511;
            int r  = j2 >> 2;
            int sg = j2 & 3;
            uint32_t sa = sbase + t * TILE_BYTES + (r * LDK + sg * 8) * 2;
            cp16(sa, gp[t] + (size_t)r * Kdim + sg * 8);
        }
        CP_COMMIT();
    }

    for (int c = 0; c < nch; c++) {
        CP_WAIT0();
        __syncthreads();

        if (c + 1 < nch) {
            int k0 = (c + 1) * 32;
            int st = (c + 1) & 1;
            const __half* gp[2] = { Ap + (size_t)m0 * Kdim, Bp + (size_t)n0 * Kdim };
            #pragma unroll
            for (int e = 0; e < 4; e++) {
                int idx = tid + e * 256;
                int t  = idx >> 9;
                int j2 = idx & 511;
                int r  = j2 >> 2;
                int sg = j2 & 3;
                uint32_t sa = sbase + st * STAGE_BYTES + t * TILE_BYTES
                            + (r * LDK + sg * 8) * 2;
                cp16(sa, gp[t] + (size_t)r * Kdim + k0 + sg * 8);
            }
            CP_COMMIT();
        }

        // ---- compute on stage c&1
        const uint32_t stb = sbase + (c & 1) * STAGE_BYTES;
        const uint32_t bA = stb;
        const uint32_t bB = stb + TILE_BYTES;

        #pragma unroll
        for (int kk = 0; kk < 2; kk++) {
            const int ko = kk * 16 + (lane >> 4) * 8;   // half offset within row
            const int ar = wm * 32 + (lane & 15);
            uint32_t amat[2][4];
            #pragma unroll
            for (int mt = 0; mt < 2; mt++)
                ldm_x4(amat[mt], bA + ((ar + mt * 16) * LDK + ko) * 2);
            uint32_t bmat[8][2];
            #pragma unroll
            for (int nt2 = 0; nt2 < 4; nt2++) {
                const int br = wn * 64 + nt2 * 16 + (lane & 15);
                uint32_t r[4];
                ldm_x4(r, bB + (br * LDK + ko) * 2);
                bmat[nt2 * 2][0] = r[0]; bmat[nt2 * 2 + 1][0] = r[1];
                bmat[nt2 * 2][1] = r[2]; bmat[nt2 * 2 + 1][1] = r[3];
            }
            #pragma unroll
            for (int mt = 0; mt < 2; mt++)
                #pragma unroll
                for (int nt = 0; nt < 8; nt++)
                    mma16816(acc[mt][nt], amat[mt], bmat[nt]);
        }
        __syncthreads();
    }

    // ---- epilogue: direct fp32 stores
    float* outb = outp + (size_t)b * Mdim * P_;
    #pragma unroll
    for (int mt = 0; mt < 2; mt++) {
        int r1 = m0 + wm * 32 + mt * 16 + (lane >> 2);
        #pragma unroll
        for (int nt = 0; nt < 8; nt++) {
            int col = n0 + wn * 64 + nt * 8 + 2 * (lane & 3);
            float2 v0 = make_float2(acc[mt][nt][0], acc[mt][nt][1]);
            float2 v1 = make_float2(acc[mt][nt][2], acc[mt][nt][3]);
            *(float2*)&outb[(size_t)r1 * P_ + col]       = v0;
            *(float2*)&outb[(size_t)(r1 + 8) * P_ + col] = v1;
        }
    }
}

// ---------------------------------------------------------------------------
// Depthwise 3x3 conv (pad 1) + exact GELU on bs channels, rolling-window,
// fused q/k sum-of-squares partials. grid (HH/16, CT, B), 256 threads.
// ---------------------------------------------------------------------------
__global__ __launch_bounds__(256) void dw_kernel(
    const float* __restrict__ w_dw,
    const float* __restrict__ w_bs_dw)
{
    __shared__ float s[18][132];
    __shared__ float red[8];
    const int y0 = blockIdx.x * 16;
    const int ch = blockIdx.y;
    const int b  = blockIdx.z;
    const int tid = threadIdx.x;

    const float* in = g_pw + ((size_t)b * CT_ + ch) * P_;
    #pragma unroll
    for (int e = 0; e < 9; e++) {
        int idx = tid + e * 256;
        int row = idx >> 7, col = idx & 127;
        int y = y0 - 1 + row;
        s[row][col + 1] = (y >= 0 && y < HH_) ? in[y * WW_ + col] : 0.f;
    }
    if (tid < 36) s[tid >> 1][(tid & 1) * 129] = 0.f;
    __syncthreads();

    const float* wp = (ch < C3_) ? (w_dw + ch * 9) : (w_bs_dw + (ch - C3_) * 9);
    float w[9];
    #pragma unroll
    for (int i = 0; i < 9; i++) w[i] = __ldg(&wp[i]);

    float* outc = g_dw + ((size_t)b * CT_ + ch) * P_;
    const int x = tid & 127;
    const int g = tid >> 7;            // 0 or 1: rows g*8 .. g*8+7
    const int rb = g * 8;

    float l0 = s[rb][x],     m0 = s[rb][x + 1],     r0 = s[rb][x + 2];
    float l1 = s[rb + 1][x], m1 = s[rb + 1][x + 1], r1 = s[rb + 1][x + 2];
    float sumsq = 0.f;

    #pragma unroll
    for (int j = 0; j < 8; j++) {
        float l2 = s[rb + j + 2][x];
        float m2 = s[rb + j + 2][x + 1];
        float r2 = s[rb + j + 2][x + 2];
        float acc = w[0] * l0 + w[1] * m0 + w[2] * r0
                  + w[3] * l1 + w[4] * m1 + w[5] * r1
                  + w[6] * l2 + w[7] * m2 + w[8] * r2;
        if (ch >= C3_)
            acc = 0.5f * acc * (1.0f + erff(acc * 0.70710678118654752f));
        outc[(y0 + rb + j) * WW_ + x] = acc;
        sumsq += acc * acc;
        l0 = l1; m0 = m1; r0 = r1;
        l1 = l2; m1 = m2; r1 = r2;
    }

    // fused q/k norm partials (channels 0..2C-1)
    if (ch < 2 * C_) {
        #pragma unroll
        for (int off = 16; off > 0; off >>= 1)
            sumsq += __shfl_xor_sync(0xFFFFFFFFu, sumsq, off);
        if ((tid & 31) == 0) red[tid >> 5] = sumsq;
        __syncthreads();
        if (tid == 0) {
            float t = red[0];
            #pragma unroll
            for (int q = 1; q < 8; q++) t += red[q];
            g_npart[(((size_t)b * 2 * C_ + ch) << 3) + blockIdx.x] = t;
        }
    }
}

// ---------------------------------------------------------------------------
// Finalize norms: one thread per (b, ch) over 8 partials
// ---------------------------------------------------------------------------
__global__ __launch_bounds__(256) void norm_fin_kernel()
{
    int idx = blockIdx.x * 256 + threadIdx.x;      // 0 .. B*768-1
    if (idx >= B_ * 2 * C_) return;
    int b = idx / (2 * C_), ch = idx % (2 * C_);
    const float* p = g_npart + ((size_t)idx << 3);
    float t = 0.f;
    #pragma unroll
    for (int q = 0; q < 8; q++) t += p[q];
    float nv = fmaxf(sqrtf(t), 1e-12f);
    if (ch < C_) g_norms[b * C_ + ch] = nv;
    else         g_norms[B_ * C_ + b * C_ + (ch - C_)] = nv;
}

// ---------------------------------------------------------------------------
// Attention logits split-K partials (f32x2)
// ---------------------------------------------------------------------------
__global__ __launch_bounds__(256) void attn_part_kernel()
{
    const int s  = blockIdx.x;   // 0..15
    const int bh = blockIdx.y;   // 0..31
    const int b = bh >> 3, h = bh & 7;

    const float* qb = g_dw + ((size_t)b * CT_ + h * CH_) * P_ + s * 1024;
    const float* kb = g_dw + ((size_t)b * CT_ + C_ + h * CH_) * P_ + s * 1024;

    __shared__ __align__(16) float qs[48][66];
    __shared__ __align__(16) float ks[48][66];

    const int tid = threadIdx.x;
    const int tx = tid & 15, ty = tid >> 4;
    const int i0 = ty * 3, j0 = tx * 3;
    unsigned long long acc[3][3];
    #pragma unroll
    for (int i = 0; i < 3; i++)
        #pragma unroll
        for (int jj = 0; jj < 3; jj++) acc[i][jj] = 0ull;

    for (int p0 = 0; p0 < 1024; p0 += 64) {
        #pragma unroll
        for (int e = 0; e < 12; e++) {
            int idx = tid + e * 256;
            int row = idx >> 6, col = idx & 63;
            qs[row][col] = qb[(size_t)row * P_ + p0 + col];
            ks[row][col] = kb[(size_t)row * P_ + p0 + col];
        }
        __syncthreads();
        #pragma unroll 8
        for (int p = 0; p < 64; p += 2) {
            unsigned long long a0 = __double_as_longlong(*(const double*)&qs[i0][p]);
            unsigned long long a1 = __double_as_longlong(*(const double*)&qs[i0 + 1][p]);
            unsigned long long a2 = __double_as_longlong(*(const double*)&qs[i0 + 2][p]);
            unsigned long long b0 = __double_as_longlong(*(const double*)&ks[j0][p]);
            unsigned long long b1 = __double_as_longlong(*(const double*)&ks[j0 + 1][p]);
            unsigned long long b2 = __double_as_longlong(*(const double*)&ks[j0 + 2][p]);
            fma_f32x2(acc[0][0], a0, b0); fma_f32x2(acc[0][1], a0, b1); fma_f32x2(acc[0][2], a0, b2);
            fma_f32x2(acc[1][0], a1, b0); fma_f32x2(acc[1][1], a1, b1); fma_f32x2(acc[1][2], a1, b2);
            fma_f32x2(acc[2][0], a2, b0); fma_f32x2(acc[2][1], a2, b1); fma_f32x2(acc[2][2], a2, b2);
        }
        __syncthreads();
    }

    float* out = g_part + ((size_t)bh * SPLITS_ + s) * (CH_ * CH_);
    #pragma unroll
    for (int i = 0; i < 3; i++)
        #pragma unroll
        for (int jj = 0; jj < 3; jj++)
            out[(i0 + i) * CH_ + j0 + jj] = f2lo(acc[i][jj]) + f2hi(acc[i][jj]);
}

// ---------------------------------------------------------------------------
// Softmax rows (with normalization by q/k norms and scale)
// ---------------------------------------------------------------------------
__global__ __launch_bounds__(64) void softmax_kernel()
{
    const int i  = blockIdx.x;
    const int bh = blockIdx.y;
    const int b = bh >> 3, h = bh & 7;
    const int j = threadIdx.x;

    float val = 0.f;
    float logit = -1e30f;
    if (j < CH_) {
        float sum = 0.f;
        #pragma unroll
        for (int s = 0; s < SPLITS_; s++)
            sum += g_part[((size_t)bh * SPLITS_ + s) * (CH_ * CH_) + i * CH_ + j];
        float nq = g_norms[b * C_ + h * CH_ + i];
        float nk = g_norms[B_ * C_ + b * C_ + h * CH_ + j];
        val = sum / (nq * nk) * SCALE_;
        logit = val;
    }
    __shared__ float red[64];
    red[j] = logit;
    __syncthreads();
    for (int off = 32; off > 0; off >>= 1) {
        if (j < off) red[j] = fmaxf(red[j], red[j + off]);
        __syncthreads();
    }
    float mx = red[0];
    __syncthreads();
    float e = (j < CH_) ? expf(val - mx) : 0.f;
    red[j] = e;
    __syncthreads();
    for (int off = 32; off > 0; off >>= 1) {
        if (j < off) red[j] += red[j + off];
        __syncthreads();
    }
    if (j < CH_) g_attn[(size_t)bh * CH_ * CH_ + i * CH_ + j] = e / red[0];
}

// ---------------------------------------------------------------------------
// out = attn @ V, written directly as fp16 into proj input cols 0..383
// grid (P/128, BH), 128 threads (one pixel each)
// ---------------------------------------------------------------------------
__global__ __launch_bounds__(128) void av_kernel()
{
    const int pb = blockIdx.x;
    const int bh = blockIdx.y;
    const int b = bh >> 3, h = bh & 7;
    const int p = pb * 128 + threadIdx.x;

    __shared__ float at[CH_ * CH_];
    for (int idx = threadIdx.x; idx < CH_ * CH_; idx += 128)
        at[idx] = g_attn[(size_t)bh * CH_ * CH_ + idx];
    __syncthreads();

    const float* vb = g_dw + ((size_t)b * CT_ + 2 * C_ + h * CH_) * P_ + p;
    float v[CH_];
    #pragma unroll
    for (int d = 0; d < CH_; d++) v[d] = vb[(size_t)d * P_];

    uint32_t hb[24];
    #pragma unroll 4
    for (int cp = 0; cp < 24; cp++) {
        float a0 = 0.f, a1 = 0.f;
        #pragma unroll
        for (int d = 0; d < CH_; d++) {
            a0 += at[(2 * cp) * CH_ + d] * v[d];
            a1 += at[(2 * cp + 1) * CH_ + d] * v[d];
        }
        hb[cp] = pack_h(__float2half(a0), __float2half(a1));
    }

    size_t base = ((size_t)b * P_ + p) * (2 * C_) + h * CH_;
    uint4* dh = (uint4*)&g_pT[base];
    #pragma unroll
    for (int q = 0; q < 6; q++) dh[q] = *(uint4*)&hb[q * 4];
}

// ---------------------------------------------------------------------------
extern "C" void kernel_launch(void* const* d_in, const int* in_sizes, int n_in,
                              void* d_out, int out_size)
{
    const float* x       = (const float*)d_in[0];
    const float* w_qkv   = (const float*)d_in[1];
    const float* w_dw    = (const float*)d_in[2];
    const float* w_proj  = (const float*)d_in[3];
    const float* w_bs_pw = (const float*)d_in[4];
    const float* w_bs_dw = (const float*)d_in[5];
    float* out = (float*)d_out;

    cudaFuncSetAttribute(gemm_mma_kernel<0>,
                         cudaFuncAttributeMaxDynamicSharedMemorySize, GEMM_SMEM);
    cudaFuncSetAttribute(gemm_mma_kernel<1>,
                         cudaFuncAttributeMaxDynamicSharedMemorySize, GEMM_SMEM);

    float* pw = nullptr;
    cudaGetSymbolAddress((void**)&pw, g_pw);

    // 0) weight convert + x transpose/convert
    {
        int total = CT_ * C_ + C_ * 2 * C_;
        conv_w_kernel<<<(total + 255) / 256, 256>>>(w_qkv, w_bs_pw, w_proj);
    }
    pack_x_kernel<<<dim3(P_ / 64, C_ / 96, B_), 256>>>(x);
    // 1) fused pointwise GEMM (pure fp16 HMMA)
    gemm_mma_kernel<0><<<dim3(P_ / 128, CT_ / 128, B_), 256, GEMM_SMEM>>>(pw);
    // 2) depthwise 3x3 (+GELU on bs channels) with fused q/k sumsq partials
    dw_kernel<<<dim3(HH_ / 16, CT_, B_), 256>>>(w_dw, w_bs_dw);
    // 3) finalize q/k L2 norms
    norm_fin_kernel<<<(B_ * 2 * C_ + 255) / 256, 256>>>();
    // 4) attention logits (split-K partials, f32x2)
    attn_part_kernel<<<dim3(SPLITS_, BH_), 256>>>();
    // 5) softmax with normalization
    softmax_kernel<<<dim3(CH_, BH_), 64>>>();
    // 6) attn @ V -> proj input cols 0..383 (fp16)
    av_kernel<<<dim3(P_ / 128, BH_), 128>>>();
    // 6b) y branch -> proj input cols 384..767 (fp16)
    pack_proj_kernel<<<dim3(P_ / 64, C_ / 96, B_), 256>>>();
    // 7) projection GEMM -> output
    gemm_mma_kernel<1><<<dim3(P_ / 128, C_ / 128, B_), 256, GEMM_SMEM>>>(out);
}